// round 11
// baseline (speedup 1.0000x reference)
#include <cuda_runtime.h>

// Problem constants
#define BB    8
#define TT    2048
#define CIN   7
#define CC    8
#define NCH   128      // chunks per batch
#define SEGC  2        // chunks per segment
#define SEGST 32       // time steps per segment
#define NSEG2 64       // segments per batch
#define NBLK  384      // persistent blocks
#define GRPB  48       // blocks per batch-group (8 groups)
#define NT    256      // threads per block
#define SIZE  4680
#define STRIDE 4736
#define O2    8
#define O3    72
#define O4    584
#define HDIM  256
#define NSL   32       // gemv slices per batch
#define SLW   147

// Scratch (device globals -- no runtime allocation)
__device__ __align__(16) float g_bufB[(size_t)BB * NCH * STRIDE];   // local prefixes
__device__ __align__(16) float g_bufA[(size_t)BB * NCH * STRIDE];   // logs
__device__ __align__(16) float g_T[(size_t)BB * NSEG2 * STRIDE];    // scanned totals
__device__ __align__(16) float g_hp[NSL * BB * HDIM];
// Per-group sync state (all zero-init; reset at end of each launch)
__device__ unsigned int g_barArr[BB];
__device__ unsigned int g_t1a[BB], g_t3a[BB], g_t4a[BB], g_ack[BB];

// ---------------------------------------------------------------------------
// Group-scoped barrier: all GRPB blocks of group b call with increasing idx.
// Co-residency: __launch_bounds__(256,3) -> 444 >= 384 total blocks resident.
// ---------------------------------------------------------------------------
__device__ __forceinline__ void gsyncg(int b, unsigned int idx)
{
    __syncthreads();
    if (threadIdx.x == 0) {
        __threadfence();
        atomicAdd(&g_barArr[b], 1u);
        unsigned int target = idx * GRPB;
        volatile unsigned int* p = &g_barArr[b];
        while (*p < target) { }
        __threadfence();
    }
    __syncthreads();
}

// ---------------------------------------------------------------------------
// Group merge Od = A (x) B. 256 threads. smem: al, bl (584 each).
// ---------------------------------------------------------------------------
__device__ void ta_merge(const float* __restrict__ A, const float* __restrict__ Bp,
                         float* __restrict__ Od, float* sm, int tid)
{
    float* al = sm;
    float* bl = sm + 584;
    for (int t = tid; t < O4; t += NT) { al[t] = __ldcg(A + t); bl[t] = __ldcg(Bp + t); }
    __syncthreads();

    for (int t = tid; t < O4; t += NT) {
        float r;
        if (t >= O3) {
            int q = t - O3;
            r = al[t] + bl[t] + al[q >> 6] * bl[O2 + (q & 63)]
              + al[O2 + (q >> 3)] * bl[q & 7];
        } else if (t >= O2) {
            int u = t - O2;
            r = al[t] + bl[t] + al[u >> 3] * bl[u & 7];
        } else {
            r = al[t] + bl[t];
        }
        Od[t] = r;
    }
    float a1r[8];
    #pragma unroll
    for (int i = 0; i < 8; i++) a1r[i] = al[i];
    float4 b1v = *(const float4*)&bl[(4 * tid) & 7];
    float4 b2v = *(const float4*)&bl[O2 + ((4 * tid) & 63)];
    float4 b3v = *(const float4*)&bl[O3 + 4 * (tid & 127)];
    #pragma unroll
    for (int m4 = 0; m4 < 4; m4++) {
        int p = 4 * tid + 1024 * m4;
        float a1 = a1r[(tid >> 7) + 2 * m4];
        float a2 = al[O2 + (tid >> 4) + 16 * m4];
        float a3 = al[O3 + (tid >> 1) + 128 * m4];
        float4 Av = __ldcg((const float4*)(A + O4 + p));
        float4 Bv = __ldcg((const float4*)(Bp + O4 + p));
        float4 o;
        o.x = Av.x + Bv.x + a1 * b3v.x + a2 * b2v.x + a3 * b1v.x;
        o.y = Av.y + Bv.y + a1 * b3v.y + a2 * b2v.y + a3 * b1v.y;
        o.z = Av.z + Bv.z + a1 * b3v.z + a2 * b2v.z + a3 * b1v.z;
        o.w = Av.w + Bv.w + a1 * b3v.w + a2 * b2v.w + a3 * b1v.w;
        *(float4*)(Od + O4 + p) = o;
    }
}

// ---------------------------------------------------------------------------
// apply+log for one chunk task (global index b*NCH+n). 256 threads.
// ---------------------------------------------------------------------------
__device__ void apply_one(int task, float* sm, int tid)
{
    int b = task >> 7, n = task & 127;
    int seg = n >> 1;                 // SEGC = 2

    float* s    = sm;
    float* al   = sm + 584;
    float* blw  = sm + 1168;
    float* P2_2 = sm + 1752;
    float* P2_3 = sm + 1824;
    float* P3_3 = sm + 2336;

    const float* L = g_bufB + (size_t)task * STRIDE;
    float4 r4v[4];

    if (seg == 0) {
        for (int t = tid; t < O4; t += NT) s[t] = __ldcg(L + t);
        #pragma unroll
        for (int m4 = 0; m4 < 4; m4++)
            r4v[m4] = __ldcg((const float4*)(L + O4 + 4 * tid + 1024 * m4));
    } else {
        const float* A = (seg == 1)
            ? g_bufB + (size_t)(b * NCH + 1) * STRIDE
            : g_T + (size_t)(b * NSEG2 + seg - 1) * STRIDE;
        for (int t = tid; t < O4; t += NT) { al[t] = __ldcg(A + t); blw[t] = __ldcg(L + t); }
        __syncthreads();
        for (int t = tid; t < O4; t += NT) {
            float r;
            if (t >= O3) {
                int q = t - O3;
                r = al[t] + blw[t]
                  + al[q >> 6]        * blw[O2 + (q & 63)]
                  + al[O2 + (q >> 3)] * blw[q & 7];
            } else if (t >= O2) {
                int u = t - O2;
                r = al[t] + blw[t] + al[u >> 3] * blw[u & 7];
            } else {
                r = al[t] + blw[t];
            }
            s[t] = r;
        }
        float a1r[8];
        #pragma unroll
        for (int i = 0; i < 8; i++) a1r[i] = al[i];
        float4 b1v = *(const float4*)&blw[(4 * tid) & 7];
        float4 b2v = *(const float4*)&blw[O2 + ((4 * tid) & 63)];
        float4 b3v = *(const float4*)&blw[O3 + 4 * (tid & 127)];
        #pragma unroll
        for (int m4 = 0; m4 < 4; m4++) {
            int p = 4 * tid + 1024 * m4;
            float a1 = a1r[(tid >> 7) + 2 * m4];
            float a2 = al[O2 + (tid >> 4) + 16 * m4];
            float a3 = al[O3 + (tid >> 1) + 128 * m4];
            float4 Av = __ldcg((const float4*)(A + O4 + p));
            float4 Lv = __ldcg((const float4*)(L + O4 + p));
            float4 o;
            o.x = Av.x + Lv.x + a1 * b3v.x + a2 * b2v.x + a3 * b1v.x;
            o.y = Av.y + Lv.y + a1 * b3v.y + a2 * b2v.y + a3 * b1v.y;
            o.z = Av.z + Lv.z + a1 * b3v.z + a2 * b2v.z + a3 * b1v.z;
            o.w = Av.w + Lv.w + a1 * b3v.w + a2 * b2v.w + a3 * b1v.w;
            r4v[m4] = o;
        }
    }
    __syncthreads();

    float s1r[8];
    #pragma unroll
    for (int i = 0; i < 8; i++) s1r[i] = s[i];
    float4 s1v = *(const float4*)&s[(4 * tid) & 7];
    float4 s2v = *(const float4*)&s[O2 + ((4 * tid) & 63)];
    float4 s3v = *(const float4*)&s[O3 + 4 * (tid & 127)];
    float s2f = s[O2 + (tid & 63)], s1f = s[tid & 7];
    float s3a = s[O3 + tid], s3b = s[O3 + tid + 256];

    #pragma unroll
    for (int m4 = 0; m4 < 4; m4++) {
        float a1 = s1r[(tid >> 7) + 2 * m4];
        float a2 = s[O2 + (tid >> 4) + 16 * m4];
        float a3 = s[O3 + (tid >> 1) + 128 * m4];
        r4v[m4].x -= 0.5f * (a1 * s3v.x + a2 * s2v.x + a3 * s1v.x);
        r4v[m4].y -= 0.5f * (a1 * s3v.y + a2 * s2v.y + a3 * s1v.y);
        r4v[m4].z -= 0.5f * (a1 * s3v.z + a2 * s2v.z + a3 * s1v.z);
        r4v[m4].w -= 0.5f * (a1 * s3v.w + a2 * s2v.w + a3 * s1v.w);
    }
    {
        float pa = s1r[tid >> 6] * s2f + s[O2 + (tid >> 3)] * s1f;
        float pb = s1r[(tid >> 6) + 4] * s2f + s[O2 + (tid >> 3) + 32] * s1f;
        P2_3[tid] = pa; P2_3[tid + 256] = pb;
    }
    if (tid < 64) P2_2[tid] = s1r[tid >> 3] * s[tid & 7];
    __syncthreads();

    {
        float4 P23v = *(const float4*)&P2_3[4 * (tid & 127)];
        float4 P22v = *(const float4*)&P2_2[(4 * tid) & 63];
        #pragma unroll
        for (int m4 = 0; m4 < 4; m4++) {
            float a1 = s1r[(tid >> 7) + 2 * m4];
            float a2 = s[O2 + (tid >> 4) + 16 * m4];
            r4v[m4].x += (1.0f / 3.0f) * (a1 * P23v.x + a2 * P22v.x);
            r4v[m4].y += (1.0f / 3.0f) * (a1 * P23v.y + a2 * P22v.y);
            r4v[m4].z += (1.0f / 3.0f) * (a1 * P23v.z + a2 * P22v.z);
            r4v[m4].w += (1.0f / 3.0f) * (a1 * P23v.w + a2 * P22v.w);
        }
        float P22a = P2_2[tid & 63];
        P3_3[tid]       = s1r[tid >> 6] * P22a;
        P3_3[tid + 256] = s1r[(tid >> 6) + 4] * P22a;
    }
    __syncthreads();

    float* S = g_bufA + (size_t)task * STRIDE;
    {
        float4 P33v = *(const float4*)&P3_3[4 * (tid & 127)];
        #pragma unroll
        for (int m4 = 0; m4 < 4; m4++) {
            float a1 = s1r[(tid >> 7) + 2 * m4];
            r4v[m4].x -= 0.25f * a1 * P33v.x;
            r4v[m4].y -= 0.25f * a1 * P33v.y;
            r4v[m4].z -= 0.25f * a1 * P33v.z;
            r4v[m4].w -= 0.25f * a1 * P33v.w;
            *(float4*)&S[O4 + 4 * tid + 1024 * m4] = r4v[m4];
        }
        S[O3 + tid]       = s3a - 0.5f * P2_3[tid]       + (1.0f / 3.0f) * P3_3[tid];
        S[O3 + tid + 256] = s3b - 0.5f * P2_3[tid + 256] + (1.0f / 3.0f) * P3_3[tid + 256];
    }
    if (tid < 64) S[O2 + tid] = s[O2 + tid] - 0.5f * P2_2[tid];
    if (tid < 8)  S[tid] = s1r[tid];
}

// ---------------------------------------------------------------------------
// THE single fused kernel: 8 independent per-batch pipelines of 48 blocks.
// ---------------------------------------------------------------------------
__global__ void __launch_bounds__(NT, 3)
k_fused(const float* __restrict__ x,
        const float* __restrict__ W1,
        const float* __restrict__ b1,
        const float* __restrict__ W2,
        const float* __restrict__ b2,
        float* __restrict__ out)
{
    __shared__ __align__(16) float sm[2848];
    __shared__ int s_task;
    int blk = blockIdx.x;
    int tid = threadIdx.x;
    int b = blk / GRPB;        // batch group 0..7
    int gblk = blk - b * GRPB; // block index within group 0..47

    // warm L2 with W1 for phase 4
    {
        size_t nbytes = (size_t)SIZE * HDIM * 4;
        size_t loff = ((size_t)blk * NT + tid) * 128;
        if (loff < nbytes)
            asm volatile("prefetch.global.L2 [%0];" :: "l"((const char*)W1 + loff));
    }

    // ============ Phase 1: 2-step-fused Chen, 64 stolen tasks/group =========
    {
        const int l = tid & 7, k = (tid >> 3) & 7, j0 = tid >> 6;
        float* d   = sm;          // 256 = [32][8]
        float* cb0 = sm + 256;    // c2 [0,64), c3 [64,576)
        float* cb1 = sm + 840;
        for (;;) {
            __syncthreads();
            if (tid == 0) s_task = (int)atomicAdd(&g_t1a[b], 1u);
            __syncthreads();
            int seg = s_task;
            if (seg >= NSEG2) break;

            {   // increments (one per thread: 32 steps x 8 ch = 256)
                int s = tid >> 3, ch = tid & 7;
                int t = seg * SEGST + s;
                float v;
                if (ch < CIN) {
                    float cur  = __ldg(&x[(b * TT + t) * CIN + ch]);
                    float prev = (t > 0) ? __ldg(&x[(b * TT + t - 1) * CIN + ch]) : 0.0f;
                    v = cur - prev;
                } else {
                    v = (t > 0) ? (1.0f / 2047.0f) : 0.0f;
                }
                d[tid] = v;
            }
            __syncthreads();

            float r4[16], c1r[8];
            // ---- iter 0: carry := F(d0, d1) ----
            {
                float al = d[l], bl = d[8 + l], ak = d[k], bk = d[8 + k];
                float bkbl = bk * bl;
                float w1 = ak * ((1.0f / 6.0f) * al + 0.5f * bl) + 0.5f * bkbl;
                float w2 = (1.0f / 6.0f) * bkbl;
                float aje = d[j0], bje = d[8 + j0], ajo = d[j0 + 4], bjo = d[8 + j0 + 4];
                float F3_e = aje * w1 + bje * w2;
                float F3_o = ajo * w1 + bjo * w2;
                float u4 = ak * ((1.0f / 24.0f) * al + (1.0f / 6.0f) * bl) + 0.25f * bkbl;
                float v4 = (1.0f / 6.0f) * bkbl;
                float ge = aje * u4 + bje * v4, he = (1.0f / 24.0f) * bje * bkbl;
                float go = ajo * u4 + bjo * v4, ho = (1.0f / 24.0f) * bjo * bkbl;
                #pragma unroll
                for (int m = 0; m < 16; m++)
                    r4[m] = d[m >> 1] * ((m & 1) ? go : ge)
                          + d[8 + (m >> 1)] * ((m & 1) ? ho : he);
                #pragma unroll
                for (int i = 0; i < 8; i++) c1r[i] = d[i] + d[8 + i];
                cb0[64 + tid] = F3_e;
                cb0[64 + tid + 256] = F3_o;
                if (tid < 64) {
                    int xx = tid >> 3, yy = tid & 7;
                    cb0[tid] = 0.5f * d[xx] * d[yy] + d[xx] * d[8 + yy]
                             + 0.5f * d[8 + xx] * d[8 + yy];
                }
                __syncthreads();
            }
            // ---- iters 1..15 ----
            for (int it = 1; it < 16; it++) {
                float* cc = (it & 1) ? cb0 : cb1;
                float* cn = (it & 1) ? cb1 : cb0;
                const float* da = d + 16 * it;
                const float* db = da + 8;
                float al = da[l], bl = db[l], ak = da[k], bk = db[k];
                float el = al + bl;
                float bkbl = bk * bl;
                float F2_kl = 0.5f * ak * al + ak * bl + 0.5f * bkbl;
                float w1 = ak * ((1.0f / 6.0f) * al + 0.5f * bl) + 0.5f * bkbl;
                float w2 = (1.0f / 6.0f) * bkbl;
                float aje = da[j0], bje = db[j0], ajo = da[j0 + 4], bjo = db[j0 + 4];
                float F3_e = aje * w1 + bje * w2;
                float F3_o = ajo * w1 + bjo * w2;
                float u4 = ak * ((1.0f / 24.0f) * al + (1.0f / 6.0f) * bl) + 0.25f * bkbl;
                float v4 = (1.0f / 6.0f) * bkbl;
                float ge = aje * u4 + bje * v4, he = (1.0f / 24.0f) * bje * bkbl;
                float go = ajo * u4 + bjo * v4, ho = (1.0f / 24.0f) * bjo * bkbl;
                #pragma unroll
                for (int m = 0; m < 16; m++) {
                    float c3v = cc[64 + (tid >> 3) + 32 * m];
                    float c2v = cc[(tid >> 6) + 4 * m];
                    float F3j = (m & 1) ? F3_o : F3_e;
                    float F4m = da[m >> 1] * ((m & 1) ? go : ge)
                              + db[m >> 1] * ((m & 1) ? ho : he);
                    r4[m] += F4m + c1r[m >> 1] * F3j + c2v * F2_kl + c3v * el;
                }
                float t3a = cc[64 + tid] + F3_e + cc[tid >> 3] * el + c1r[j0] * F2_kl;
                float t3b = cc[64 + tid + 256] + F3_o + cc[(tid >> 3) + 32] * el
                          + c1r[j0 + 4] * F2_kl;
                float t2v = 0.0f;
                if (tid < 64) {
                    int xx = tid >> 3, yy = tid & 7;
                    t2v = cc[tid] + 0.5f * da[xx] * da[yy] + da[xx] * db[yy]
                        + 0.5f * db[xx] * db[yy] + c1r[xx] * (da[yy] + db[yy]);
                }
                #pragma unroll
                for (int i = 0; i < 8; i++) c1r[i] += da[i] + db[i];
                cn[64 + tid] = t3a;
                cn[64 + tid + 256] = t3b;
                if (tid < 64) cn[tid] = t2v;
                __syncthreads();
                if ((it & 7) == 7) {   // chunk snapshot
                    float* o = g_bufB + (size_t)(b * NCH + seg * SEGC + (it >> 3)) * STRIDE;
                    o[O3 + tid] = t3a;
                    o[O3 + tid + 256] = t3b;
                    if (tid < 64) o[O2 + tid] = t2v;
                    if (tid < 8)  o[tid] = c1r[tid];
                    #pragma unroll
                    for (int m = 0; m < 16; m++) o[O4 + tid + 256 * m] = r4[m];
                }
            }
        }
    }
    gsyncg(b, 1);

    // ============ Phase 2: Sklansky over 64 segment totals (per group) ======
    // 6 rounds; 32 merges per round done by gblk 0..31.
    for (int r = 0; r < 6; r++) {
        if (gblk < 32) {
            int g = gblk;
            int span = 1 << r;
            int base = (g >> r) << (r + 1);
            int e_src = base + span - 1;
            int e_dst = base + span + (g & (span - 1));
            bool bnew = (g & (span - 1)) == 0;
            const float* A = (r == 0)
                ? g_bufB + (size_t)(b * NCH + e_src * SEGC + SEGC - 1) * STRIDE
                : g_T + (size_t)(b * NSEG2 + e_src) * STRIDE;
            const float* Bp = bnew
                ? g_bufB + (size_t)(b * NCH + e_dst * SEGC + SEGC - 1) * STRIDE
                : g_T + (size_t)(b * NSEG2 + e_dst) * STRIDE;
            float* Od = g_T + (size_t)(b * NSEG2 + e_dst) * STRIDE;
            __syncthreads();
            ta_merge(A, Bp, Od, sm, tid);
        }
        gsyncg(b, 2 + r);
    }

    // ============ Phase 3: apply + log, 128 stolen tasks/group ==============
    for (;;) {
        __syncthreads();
        if (tid == 0) s_task = (int)atomicAdd(&g_t3a[b], 1u);
        __syncthreads();
        int n = s_task;
        if (n >= NCH) break;
        apply_one(b * NCH + n, sm, tid);
    }
    gsyncg(b, 8);

    // ============ Phase 4: pool + GEMV partials, 32 stolen tasks/group ======
    for (;;) {
        __syncthreads();
        if (tid == 0) s_task = (int)atomicAdd(&g_t4a[b], 1u);
        __syncthreads();
        int sl = s_task;
        if (sl >= NSL) break;
        int i0 = sl * SLW;
        int len = SIZE - i0; if (len > SLW) len = SLW;
        float* pv = sm;
        if (tid < len) {
            const float* p = g_bufA + (size_t)b * NCH * STRIDE + i0 + tid;
            float acc = 0.0f;
            #pragma unroll 8
            for (int n = 0; n < NCH; n++) acc += __ldcg(p + (size_t)n * STRIDE);
            pv[tid] = acc * (1.0f / NCH);
        }
        __syncthreads();
        float acc = 0.0f;
        for (int ii = 0; ii < len; ii++)
            acc = fmaf(pv[ii], __ldg(&W1[(size_t)(i0 + ii) * HDIM + tid]), acc);
        g_hp[(sl * BB + b) * HDIM + tid] = acc;
    }
    gsyncg(b, 9);

    // ============ Final: MLP head (group leader) ============================
    if (gblk == 0) {
        float* red = sm;
        __syncthreads();
        float h = 0.0f;
        #pragma unroll
        for (int sl2 = 0; sl2 < NSL; sl2++)
            h += __ldcg(&g_hp[(sl2 * BB + b) * HDIM + tid]);
        float v = fmaxf(h + b1[tid], 0.0f) * W2[tid];
        red[tid] = v; __syncthreads();
        for (int s2 = 128; s2 > 0; s2 >>= 1) {
            if (tid < s2) red[tid] += red[tid + s2];
            __syncthreads();
        }
        if (tid == 0) out[b] = red[0] + b2[0];
        __syncthreads();
    }

    // ============ Ack + deterministic counter reset (race-free) =============
    if (tid == 0) atomicAdd(&g_ack[b], 1u);
    if (gblk == 0 && tid == 0) {
        volatile unsigned int* p = &g_ack[b];
        while (*p < GRPB) { }        // all group blocks past final barrier
        g_barArr[b] = 0u;
        g_t1a[b] = 0u; g_t3a[b] = 0u; g_t4a[b] = 0u;
        g_ack[b] = 0u;
    }
}

// ---------------------------------------------------------------------------
extern "C" void kernel_launch(void* const* d_in, const int* in_sizes, int n_in,
                              void* d_out, int out_size)
{
    const float* x  = (const float*)d_in[0];
    const float* W1 = (const float*)d_in[1];
    const float* b1 = (const float*)d_in[2];
    const float* W2 = (const float*)d_in[3];
    const float* b2 = (const float*)d_in[4];
    float* out = (float*)d_out;

    (void)in_sizes; (void)n_in; (void)out_size;

    k_fused<<<NBLK, NT>>>(x, W1, b1, W2, b2, out);
}

// round 12
// speedup vs baseline: 1.1587x; 1.1587x over previous
#include <cuda_runtime.h>

// Problem constants
#define BB    8
#define TT    2048
#define CIN   7
#define CC    8
#define NCH   128      // chunks per batch
#define SEGC  2        // chunks per segment
#define SEGST 32       // time steps per segment
#define NSEG2 64       // segments per batch
#define NBLK  384      // persistent blocks
#define NT    256      // threads per block
#define SIZE  4680
#define STRIDE 4736
#define O2    8
#define O3    72
#define O4    584
#define HDIM  256
#define NSL   32       // gemv slices
#define SLW   147

#define NTASK1 (BB * NSEG2)    // 512 chen tasks
#define NTASK3 (BB * NCH)      // 1024 apply tasks
#define NTASK4 (BB * NSL)      // 256 gemv tasks

// Scratch (device globals -- no runtime allocation)
__device__ __align__(16) float g_bufB[(size_t)BB * NCH * STRIDE];   // local prefixes
__device__ __align__(16) float g_T[(size_t)BB * NSEG2 * STRIDE];    // scanned totals
__device__ __align__(16) float g_pool[BB * SIZE];                   // atomic log sums
__device__ __align__(16) float g_hp[NSL * BB * HDIM];
// Sync state: each counter on its OWN 128B line (no false sharing between
// barrier polling and task-steal atomics).
__device__ __align__(128) unsigned int g_bar[32];
__device__ __align__(128) unsigned int g_t1[32];
__device__ __align__(128) unsigned int g_t3[32];
__device__ __align__(128) unsigned int g_t4[32];

// ---------------------------------------------------------------------------
// Device-wide barrier. Co-residency: __launch_bounds__(256,3) -> 444 >= 384.
// ---------------------------------------------------------------------------
__device__ __forceinline__ void gsync(unsigned int idx)
{
    __syncthreads();
    if (threadIdx.x == 0) {
        __threadfence();
        atomicAdd(&g_bar[0], 1u);
        unsigned int target = idx * NBLK;
        volatile unsigned int* p = &g_bar[0];
        while (*p < target) { }
        __threadfence();
    }
    __syncthreads();
}

// ---------------------------------------------------------------------------
// Group merge Od = A (x) B. 256 threads. smem: al, bl (584 each).
// ---------------------------------------------------------------------------
__device__ void ta_merge(const float* __restrict__ A, const float* __restrict__ Bp,
                         float* __restrict__ Od, float* sm, int tid)
{
    float* al = sm;
    float* bl = sm + 584;
    for (int t = tid; t < O4; t += NT) { al[t] = __ldcg(A + t); bl[t] = __ldcg(Bp + t); }
    __syncthreads();

    for (int t = tid; t < O4; t += NT) {
        float r;
        if (t >= O3) {
            int q = t - O3;
            r = al[t] + bl[t] + al[q >> 6] * bl[O2 + (q & 63)]
              + al[O2 + (q >> 3)] * bl[q & 7];
        } else if (t >= O2) {
            int u = t - O2;
            r = al[t] + bl[t] + al[u >> 3] * bl[u & 7];
        } else {
            r = al[t] + bl[t];
        }
        Od[t] = r;
    }
    float a1r[8];
    #pragma unroll
    for (int i = 0; i < 8; i++) a1r[i] = al[i];
    float4 b1v = *(const float4*)&bl[(4 * tid) & 7];
    float4 b2v = *(const float4*)&bl[O2 + ((4 * tid) & 63)];
    float4 b3v = *(const float4*)&bl[O3 + 4 * (tid & 127)];
    #pragma unroll
    for (int m4 = 0; m4 < 4; m4++) {
        int p = 4 * tid + 1024 * m4;
        float a1 = a1r[(tid >> 7) + 2 * m4];
        float a2 = al[O2 + (tid >> 4) + 16 * m4];
        float a3 = al[O3 + (tid >> 1) + 128 * m4];
        float4 Av = __ldcg((const float4*)(A + O4 + p));
        float4 Bv = __ldcg((const float4*)(Bp + O4 + p));
        float4 o;
        o.x = Av.x + Bv.x + a1 * b3v.x + a2 * b2v.x + a3 * b1v.x;
        o.y = Av.y + Bv.y + a1 * b3v.y + a2 * b2v.y + a3 * b1v.y;
        o.z = Av.z + Bv.z + a1 * b3v.z + a2 * b2v.z + a3 * b1v.z;
        o.w = Av.w + Bv.w + a1 * b3v.w + a2 * b2v.w + a3 * b1v.w;
        *(float4*)(Od + O4 + p) = o;
    }
}

// ---------------------------------------------------------------------------
// apply+log for one chunk task; result accumulated into g_pool via REDG.
// ---------------------------------------------------------------------------
__device__ void apply_one(int task, float* sm, int tid)
{
    int b = task >> 7, n = task & 127;
    int seg = n >> 1;                 // SEGC = 2

    float* s    = sm;
    float* al   = sm + 584;
    float* blw  = sm + 1168;
    float* P2_2 = sm + 1752;
    float* P2_3 = sm + 1824;
    float* P3_3 = sm + 2336;

    const float* L = g_bufB + (size_t)task * STRIDE;
    float4 r4v[4];

    if (seg == 0) {
        for (int t = tid; t < O4; t += NT) s[t] = __ldcg(L + t);
        #pragma unroll
        for (int m4 = 0; m4 < 4; m4++)
            r4v[m4] = __ldcg((const float4*)(L + O4 + 4 * tid + 1024 * m4));
    } else {
        const float* A = (seg == 1)
            ? g_bufB + (size_t)(b * NCH + 1) * STRIDE
            : g_T + (size_t)(b * NSEG2 + seg - 1) * STRIDE;
        for (int t = tid; t < O4; t += NT) { al[t] = __ldcg(A + t); blw[t] = __ldcg(L + t); }
        __syncthreads();
        for (int t = tid; t < O4; t += NT) {
            float r;
            if (t >= O3) {
                int q = t - O3;
                r = al[t] + blw[t]
                  + al[q >> 6]        * blw[O2 + (q & 63)]
                  + al[O2 + (q >> 3)] * blw[q & 7];
            } else if (t >= O2) {
                int u = t - O2;
                r = al[t] + blw[t] + al[u >> 3] * blw[u & 7];
            } else {
                r = al[t] + blw[t];
            }
            s[t] = r;
        }
        float a1r[8];
        #pragma unroll
        for (int i = 0; i < 8; i++) a1r[i] = al[i];
        float4 b1v = *(const float4*)&blw[(4 * tid) & 7];
        float4 b2v = *(const float4*)&blw[O2 + ((4 * tid) & 63)];
        float4 b3v = *(const float4*)&blw[O3 + 4 * (tid & 127)];
        #pragma unroll
        for (int m4 = 0; m4 < 4; m4++) {
            int p = 4 * tid + 1024 * m4;
            float a1 = a1r[(tid >> 7) + 2 * m4];
            float a2 = al[O2 + (tid >> 4) + 16 * m4];
            float a3 = al[O3 + (tid >> 1) + 128 * m4];
            float4 Av = __ldcg((const float4*)(A + O4 + p));
            float4 Lv = __ldcg((const float4*)(L + O4 + p));
            float4 o;
            o.x = Av.x + Lv.x + a1 * b3v.x + a2 * b2v.x + a3 * b1v.x;
            o.y = Av.y + Lv.y + a1 * b3v.y + a2 * b2v.y + a3 * b1v.y;
            o.z = Av.z + Lv.z + a1 * b3v.z + a2 * b2v.z + a3 * b1v.z;
            o.w = Av.w + Lv.w + a1 * b3v.w + a2 * b2v.w + a3 * b1v.w;
            r4v[m4] = o;
        }
    }
    __syncthreads();

    float s1r[8];
    #pragma unroll
    for (int i = 0; i < 8; i++) s1r[i] = s[i];
    float4 s1v = *(const float4*)&s[(4 * tid) & 7];
    float4 s2v = *(const float4*)&s[O2 + ((4 * tid) & 63)];
    float4 s3v = *(const float4*)&s[O3 + 4 * (tid & 127)];
    float s2f = s[O2 + (tid & 63)], s1f = s[tid & 7];
    float s3a = s[O3 + tid], s3b = s[O3 + tid + 256];

    #pragma unroll
    for (int m4 = 0; m4 < 4; m4++) {
        float a1 = s1r[(tid >> 7) + 2 * m4];
        float a2 = s[O2 + (tid >> 4) + 16 * m4];
        float a3 = s[O3 + (tid >> 1) + 128 * m4];
        r4v[m4].x -= 0.5f * (a1 * s3v.x + a2 * s2v.x + a3 * s1v.x);
        r4v[m4].y -= 0.5f * (a1 * s3v.y + a2 * s2v.y + a3 * s1v.y);
        r4v[m4].z -= 0.5f * (a1 * s3v.z + a2 * s2v.z + a3 * s1v.z);
        r4v[m4].w -= 0.5f * (a1 * s3v.w + a2 * s2v.w + a3 * s1v.w);
    }
    {
        float pa = s1r[tid >> 6] * s2f + s[O2 + (tid >> 3)] * s1f;
        float pb = s1r[(tid >> 6) + 4] * s2f + s[O2 + (tid >> 3) + 32] * s1f;
        P2_3[tid] = pa; P2_3[tid + 256] = pb;
    }
    if (tid < 64) P2_2[tid] = s1r[tid >> 3] * s[tid & 7];
    __syncthreads();

    {
        float4 P23v = *(const float4*)&P2_3[4 * (tid & 127)];
        float4 P22v = *(const float4*)&P2_2[(4 * tid) & 63];
        #pragma unroll
        for (int m4 = 0; m4 < 4; m4++) {
            float a1 = s1r[(tid >> 7) + 2 * m4];
            float a2 = s[O2 + (tid >> 4) + 16 * m4];
            r4v[m4].x += (1.0f / 3.0f) * (a1 * P23v.x + a2 * P22v.x);
            r4v[m4].y += (1.0f / 3.0f) * (a1 * P23v.y + a2 * P22v.y);
            r4v[m4].z += (1.0f / 3.0f) * (a1 * P23v.z + a2 * P22v.z);
            r4v[m4].w += (1.0f / 3.0f) * (a1 * P23v.w + a2 * P22v.w);
        }
        float P22a = P2_2[tid & 63];
        P3_3[tid]       = s1r[tid >> 6] * P22a;
        P3_3[tid + 256] = s1r[(tid >> 6) + 4] * P22a;
    }
    __syncthreads();

    // fold p4 and accumulate straight into g_pool (REDG, no return)
    float* P = g_pool + b * SIZE;
    {
        float4 P33v = *(const float4*)&P3_3[4 * (tid & 127)];
        #pragma unroll
        for (int m4 = 0; m4 < 4; m4++) {
            float a1 = s1r[(tid >> 7) + 2 * m4];
            int p = 4 * tid + 1024 * m4;
            atomicAdd(&P[O4 + p + 0], r4v[m4].x - 0.25f * a1 * P33v.x);
            atomicAdd(&P[O4 + p + 1], r4v[m4].y - 0.25f * a1 * P33v.y);
            atomicAdd(&P[O4 + p + 2], r4v[m4].z - 0.25f * a1 * P33v.z);
            atomicAdd(&P[O4 + p + 3], r4v[m4].w - 0.25f * a1 * P33v.w);
        }
        atomicAdd(&P[O3 + tid],       s3a - 0.5f * P2_3[tid]       + (1.0f / 3.0f) * P3_3[tid]);
        atomicAdd(&P[O3 + tid + 256], s3b - 0.5f * P2_3[tid + 256] + (1.0f / 3.0f) * P3_3[tid + 256]);
    }
    if (tid < 64) atomicAdd(&P[O2 + tid], s[O2 + tid] - 0.5f * P2_2[tid]);
    if (tid < 8)  atomicAdd(&P[tid], s1r[tid]);
}

// ---------------------------------------------------------------------------
// THE single fused kernel. 384 blocks x 256 threads (3/SM), work-stealing.
// ---------------------------------------------------------------------------
__global__ void __launch_bounds__(NT, 3)
k_fused(const float* __restrict__ x,
        const float* __restrict__ W1,
        const float* __restrict__ b1,
        const float* __restrict__ W2,
        const float* __restrict__ b2,
        float* __restrict__ out)
{
    __shared__ __align__(16) float sm[2848];
    __shared__ int s_task;
    int blk = blockIdx.x;
    int tid = threadIdx.x;

    // prologue: zero pool accumulator (consumed only after gsync(8));
    // warm L2 with W1 for phase 4
    {
        int gi = blk * NT + tid;
        if (gi < BB * SIZE) g_pool[gi] = 0.0f;
        size_t nbytes = (size_t)SIZE * HDIM * 4;
        size_t loff = (size_t)gi * 128;
        if (loff < nbytes)
            asm volatile("prefetch.global.L2 [%0];" :: "l"((const char*)W1 + loff));
    }

    // ============ Phase 1: 2-step-fused Chen, 512 stolen tasks =============
    {
        const int l = tid & 7, k = (tid >> 3) & 7, j0 = tid >> 6;
        float* d   = sm;          // 256 = [32][8]
        float* cb0 = sm + 256;    // c2 [0,64), c3 [64,576)
        float* cb1 = sm + 840;
        for (;;) {
            __syncthreads();
            if (tid == 0) s_task = (int)atomicAdd(&g_t1[0], 1u);
            __syncthreads();
            int task = s_task;
            if (task >= NTASK1) break;
            int b = task >> 6, seg = task & 63;

            {   // increments (one per thread: 32 steps x 8 ch = 256)
                int s = tid >> 3, ch = tid & 7;
                int t = seg * SEGST + s;
                float v;
                if (ch < CIN) {
                    float cur  = __ldg(&x[(b * TT + t) * CIN + ch]);
                    float prev = (t > 0) ? __ldg(&x[(b * TT + t - 1) * CIN + ch]) : 0.0f;
                    v = cur - prev;
                } else {
                    v = (t > 0) ? (1.0f / 2047.0f) : 0.0f;
                }
                d[tid] = v;
            }
            __syncthreads();

            float r4[16], c1r[8];
            // ---- iter 0: carry := F(d0, d1) ----
            {
                float al = d[l], bl = d[8 + l], ak = d[k], bk = d[8 + k];
                float bkbl = bk * bl;
                float w1 = ak * ((1.0f / 6.0f) * al + 0.5f * bl) + 0.5f * bkbl;
                float w2 = (1.0f / 6.0f) * bkbl;
                float aje = d[j0], bje = d[8 + j0], ajo = d[j0 + 4], bjo = d[8 + j0 + 4];
                float F3_e = aje * w1 + bje * w2;
                float F3_o = ajo * w1 + bjo * w2;
                float u4 = ak * ((1.0f / 24.0f) * al + (1.0f / 6.0f) * bl) + 0.25f * bkbl;
                float v4 = (1.0f / 6.0f) * bkbl;
                float ge = aje * u4 + bje * v4, he = (1.0f / 24.0f) * bje * bkbl;
                float go = ajo * u4 + bjo * v4, ho = (1.0f / 24.0f) * bjo * bkbl;
                #pragma unroll
                for (int m = 0; m < 16; m++)
                    r4[m] = d[m >> 1] * ((m & 1) ? go : ge)
                          + d[8 + (m >> 1)] * ((m & 1) ? ho : he);
                #pragma unroll
                for (int i = 0; i < 8; i++) c1r[i] = d[i] + d[8 + i];
                cb0[64 + tid] = F3_e;
                cb0[64 + tid + 256] = F3_o;
                if (tid < 64) {
                    int xx = tid >> 3, yy = tid & 7;
                    cb0[tid] = 0.5f * d[xx] * d[yy] + d[xx] * d[8 + yy]
                             + 0.5f * d[8 + xx] * d[8 + yy];
                }
                __syncthreads();
            }
            // ---- iters 1..15 ----
            for (int it = 1; it < 16; it++) {
                float* cc = (it & 1) ? cb0 : cb1;
                float* cn = (it & 1) ? cb1 : cb0;
                const float* da = d + 16 * it;
                const float* db = da + 8;
                float al = da[l], bl = db[l], ak = da[k], bk = db[k];
                float el = al + bl;
                float bkbl = bk * bl;
                float F2_kl = 0.5f * ak * al + ak * bl + 0.5f * bkbl;
                float w1 = ak * ((1.0f / 6.0f) * al + 0.5f * bl) + 0.5f * bkbl;
                float w2 = (1.0f / 6.0f) * bkbl;
                float aje = da[j0], bje = db[j0], ajo = da[j0 + 4], bjo = db[j0 + 4];
                float F3_e = aje * w1 + bje * w2;
                float F3_o = ajo * w1 + bjo * w2;
                float u4 = ak * ((1.0f / 24.0f) * al + (1.0f / 6.0f) * bl) + 0.25f * bkbl;
                float v4 = (1.0f / 6.0f) * bkbl;
                float ge = aje * u4 + bje * v4, he = (1.0f / 24.0f) * bje * bkbl;
                float go = ajo * u4 + bjo * v4, ho = (1.0f / 24.0f) * bjo * bkbl;
                #pragma unroll
                for (int m = 0; m < 16; m++) {
                    float c3v = cc[64 + (tid >> 3) + 32 * m];
                    float c2v = cc[(tid >> 6) + 4 * m];
                    float F3j = (m & 1) ? F3_o : F3_e;
                    float F4m = da[m >> 1] * ((m & 1) ? go : ge)
                              + db[m >> 1] * ((m & 1) ? ho : he);
                    r4[m] += F4m + c1r[m >> 1] * F3j + c2v * F2_kl + c3v * el;
                }
                float t3a = cc[64 + tid] + F3_e + cc[tid >> 3] * el + c1r[j0] * F2_kl;
                float t3b = cc[64 + tid + 256] + F3_o + cc[(tid >> 3) + 32] * el
                          + c1r[j0 + 4] * F2_kl;
                float t2v = 0.0f;
                if (tid < 64) {
                    int xx = tid >> 3, yy = tid & 7;
                    t2v = cc[tid] + 0.5f * da[xx] * da[yy] + da[xx] * db[yy]
                        + 0.5f * db[xx] * db[yy] + c1r[xx] * (da[yy] + db[yy]);
                }
                #pragma unroll
                for (int i = 0; i < 8; i++) c1r[i] += da[i] + db[i];
                cn[64 + tid] = t3a;
                cn[64 + tid + 256] = t3b;
                if (tid < 64) cn[tid] = t2v;
                __syncthreads();
                if ((it & 7) == 7) {   // chunk snapshot
                    float* o = g_bufB + (size_t)(b * NCH + seg * SEGC + (it >> 3)) * STRIDE;
                    o[O3 + tid] = t3a;
                    o[O3 + tid + 256] = t3b;
                    if (tid < 64) o[O2 + tid] = t2v;
                    if (tid < 8)  o[tid] = c1r[tid];
                    #pragma unroll
                    for (int m = 0; m < 16; m++) o[O4 + tid + 256 * m] = r4[m];
                }
            }
        }
    }
    gsync(1);

    // ============ Phase 2: Sklansky over 64 segment totals ==================
    for (int r = 0; r < 6; r++) {
        if (blk < 256) {
            int b = blk >> 5, g = blk & 31;
            int span = 1 << r;
            int base = (g >> r) << (r + 1);
            int e_src = base + span - 1;
            int e_dst = base + span + (g & (span - 1));
            bool bnew = (g & (span - 1)) == 0;
            const float* A = (r == 0)
                ? g_bufB + (size_t)(b * NCH + e_src * SEGC + SEGC - 1) * STRIDE
                : g_T + (size_t)(b * NSEG2 + e_src) * STRIDE;
            const float* Bp = bnew
                ? g_bufB + (size_t)(b * NCH + e_dst * SEGC + SEGC - 1) * STRIDE
                : g_T + (size_t)(b * NSEG2 + e_dst) * STRIDE;
            float* Od = g_T + (size_t)(b * NSEG2 + e_dst) * STRIDE;
            __syncthreads();
            ta_merge(A, Bp, Od, sm, tid);
        }
        gsync(2 + r);
    }

    // ============ Phase 3: apply + log + pool-accumulate, 1024 tasks ========
    for (;;) {
        __syncthreads();
        if (tid == 0) s_task = (int)atomicAdd(&g_t3[0], 1u);
        __syncthreads();
        int task = s_task;
        if (task >= NTASK3) break;
        apply_one(task, sm, tid);
    }
    gsync(8);

    // ============ Phase 4: GEMV partials (pool already built), 256 tasks ====
    for (;;) {
        __syncthreads();
        if (tid == 0) s_task = (int)atomicAdd(&g_t4[0], 1u);
        __syncthreads();
        int task = s_task;
        if (task >= NTASK4) break;
        int b = task >> 5, sl = task & 31;
        int i0 = sl * SLW;
        int len = SIZE - i0; if (len > SLW) len = SLW;
        float* pv = sm;
        if (tid < len)
            pv[tid] = __ldcg(&g_pool[b * SIZE + i0 + tid]) * (1.0f / NCH);
        __syncthreads();
        float acc = 0.0f;
        for (int ii = 0; ii < len; ii++)
            acc = fmaf(pv[ii], __ldg(&W1[(size_t)(i0 + ii) * HDIM + tid]), acc);
        g_hp[(sl * BB + b) * HDIM + tid] = acc;
    }
    gsync(9);

    // ============ Final: MLP head (block 0) =================================
    if (blk == 0) {
        float* red = sm;
        __syncthreads();
        for (int bb = 0; bb < BB; bb++) {
            float h = 0.0f;
            #pragma unroll
            for (int sl2 = 0; sl2 < NSL; sl2++)
                h += __ldcg(&g_hp[(sl2 * BB + bb) * HDIM + tid]);
            float v = fmaxf(h + b1[tid], 0.0f) * W2[tid];
            red[tid] = v; __syncthreads();
            for (int s2 = 128; s2 > 0; s2 >>= 1) {
                if (tid < s2) red[tid] += red[tid + s2];
                __syncthreads();
            }
            if (tid == 0) out[bb] = red[0] + b2[0];
            __syncthreads();
        }
        if (tid == 0) { g_bar[0] = 0u; g_t1[0] = 0u; g_t3[0] = 0u; g_t4[0] = 0u; }
    }
}

// ---------------------------------------------------------------------------
extern "C" void kernel_launch(void* const* d_in, const int* in_sizes, int n_in,
                              void* d_out, int out_size)
{
    const float* x  = (const float*)d_in[0];
    const float* W1 = (const float*)d_in[1];
    const float* b1 = (const float*)d_in[2];
    const float* W2 = (const float*)d_in[3];
    const float* b2 = (const float*)d_in[4];
    float* out = (float*)d_out;

    (void)in_sizes; (void)n_in; (void)out_size;

    k_fused<<<NBLK, NT>>>(x, W1, b1, W2, b2, out);
}

// round 13
// speedup vs baseline: 1.3053x; 1.1266x over previous
#include <cuda_runtime.h>

// Problem constants
#define BB    8
#define TT    2048
#define CIN   7
#define CC    8
#define NCH   128      // chunks per batch
#define SEGC  2        // chunks per segment
#define SEGST 32       // time steps per segment
#define NSEG2 64       // segments per batch
#define NBLK  384      // persistent blocks
#define NT    256      // threads per block
#define SIZE  4680
#define STRIDE 4736
#define O2    8
#define O3    72
#define O4    584
#define HDIM  256
#define NSL   32       // gemv slices
#define SLW   147

#define NTASK1 (BB * NSEG2)    // 512 chen tasks
#define NTASK3 (BB * NCH)      // 1024 apply tasks
#define NTASK4 (BB * NSL)      // 256 pool/gemv tasks

// Scratch (device globals -- no runtime allocation)
__device__ __align__(16) float g_bufB[(size_t)BB * NCH * STRIDE];   // local prefixes
__device__ __align__(16) float g_bufA[(size_t)BB * NCH * STRIDE];   // logs
__device__ __align__(16) float g_T[(size_t)BB * NSEG2 * STRIDE];    // scanned totals
__device__ __align__(16) float g_hp[NSL * BB * HDIM];
// Sync state: each counter on its OWN 128B line (no false sharing between
// barrier polling and task-steal atomics).
__device__ __align__(128) unsigned int g_bar[32];
__device__ __align__(128) unsigned int g_t1[32];
__device__ __align__(128) unsigned int g_t3[32];
__device__ __align__(128) unsigned int g_t4[32];

// ---------------------------------------------------------------------------
// Device-wide barrier. Co-residency: __launch_bounds__(256,3) -> 444 >= 384.
// ---------------------------------------------------------------------------
__device__ __forceinline__ void gsync(unsigned int idx)
{
    __syncthreads();
    if (threadIdx.x == 0) {
        __threadfence();
        atomicAdd(&g_bar[0], 1u);
        unsigned int target = idx * NBLK;
        volatile unsigned int* p = &g_bar[0];
        while (*p < target) { }
        __threadfence();
    }
    __syncthreads();
}

// ---------------------------------------------------------------------------
// Group merge Od = A (x) B. 256 threads. smem: al, bl (584 each).
// ---------------------------------------------------------------------------
__device__ void ta_merge(const float* __restrict__ A, const float* __restrict__ Bp,
                         float* __restrict__ Od, float* sm, int tid)
{
    float* al = sm;
    float* bl = sm + 584;
    for (int t = tid; t < O4; t += NT) { al[t] = __ldcg(A + t); bl[t] = __ldcg(Bp + t); }
    __syncthreads();

    for (int t = tid; t < O4; t += NT) {
        float r;
        if (t >= O3) {
            int q = t - O3;
            r = al[t] + bl[t] + al[q >> 6] * bl[O2 + (q & 63)]
              + al[O2 + (q >> 3)] * bl[q & 7];
        } else if (t >= O2) {
            int u = t - O2;
            r = al[t] + bl[t] + al[u >> 3] * bl[u & 7];
        } else {
            r = al[t] + bl[t];
        }
        Od[t] = r;
    }
    float a1r[8];
    #pragma unroll
    for (int i = 0; i < 8; i++) a1r[i] = al[i];
    float4 b1v = *(const float4*)&bl[(4 * tid) & 7];
    float4 b2v = *(const float4*)&bl[O2 + ((4 * tid) & 63)];
    float4 b3v = *(const float4*)&bl[O3 + 4 * (tid & 127)];
    #pragma unroll
    for (int m4 = 0; m4 < 4; m4++) {
        int p = 4 * tid + 1024 * m4;
        float a1 = a1r[(tid >> 7) + 2 * m4];
        float a2 = al[O2 + (tid >> 4) + 16 * m4];
        float a3 = al[O3 + (tid >> 1) + 128 * m4];
        float4 Av = __ldcg((const float4*)(A + O4 + p));
        float4 Bv = __ldcg((const float4*)(Bp + O4 + p));
        float4 o;
        o.x = Av.x + Bv.x + a1 * b3v.x + a2 * b2v.x + a3 * b1v.x;
        o.y = Av.y + Bv.y + a1 * b3v.y + a2 * b2v.y + a3 * b1v.y;
        o.z = Av.z + Bv.z + a1 * b3v.z + a2 * b2v.z + a3 * b1v.z;
        o.w = Av.w + Bv.w + a1 * b3v.w + a2 * b2v.w + a3 * b1v.w;
        *(float4*)(Od + O4 + p) = o;
    }
}

// ---------------------------------------------------------------------------
// apply+log for one chunk task. 256 threads. sm: 2848 floats.
// ---------------------------------------------------------------------------
__device__ void apply_one(int task, float* sm, int tid)
{
    int b = task >> 7, n = task & 127;
    int seg = n >> 1;                 // SEGC = 2

    float* s    = sm;
    float* al   = sm + 584;
    float* blw  = sm + 1168;
    float* P2_2 = sm + 1752;
    float* P2_3 = sm + 1824;
    float* P3_3 = sm + 2336;

    const float* L = g_bufB + (size_t)task * STRIDE;
    float4 r4v[4];

    if (seg == 0) {
        for (int t = tid; t < O4; t += NT) s[t] = __ldcg(L + t);
        #pragma unroll
        for (int m4 = 0; m4 < 4; m4++)
            r4v[m4] = __ldcg((const float4*)(L + O4 + 4 * tid + 1024 * m4));
    } else {
        const float* A = (seg == 1)
            ? g_bufB + (size_t)(b * NCH + 1) * STRIDE
            : g_T + (size_t)(b * NSEG2 + seg - 1) * STRIDE;
        for (int t = tid; t < O4; t += NT) { al[t] = __ldcg(A + t); blw[t] = __ldcg(L + t); }
        __syncthreads();
        for (int t = tid; t < O4; t += NT) {
            float r;
            if (t >= O3) {
                int q = t - O3;
                r = al[t] + blw[t]
                  + al[q >> 6]        * blw[O2 + (q & 63)]
                  + al[O2 + (q >> 3)] * blw[q & 7];
            } else if (t >= O2) {
                int u = t - O2;
                r = al[t] + blw[t] + al[u >> 3] * blw[u & 7];
            } else {
                r = al[t] + blw[t];
            }
            s[t] = r;
        }
        float a1r[8];
        #pragma unroll
        for (int i = 0; i < 8; i++) a1r[i] = al[i];
        float4 b1v = *(const float4*)&blw[(4 * tid) & 7];
        float4 b2v = *(const float4*)&blw[O2 + ((4 * tid) & 63)];
        float4 b3v = *(const float4*)&blw[O3 + 4 * (tid & 127)];
        #pragma unroll
        for (int m4 = 0; m4 < 4; m4++) {
            int p = 4 * tid + 1024 * m4;
            float a1 = a1r[(tid >> 7) + 2 * m4];
            float a2 = al[O2 + (tid >> 4) + 16 * m4];
            float a3 = al[O3 + (tid >> 1) + 128 * m4];
            float4 Av = __ldcg((const float4*)(A + O4 + p));
            float4 Lv = __ldcg((const float4*)(L + O4 + p));
            float4 o;
            o.x = Av.x + Lv.x + a1 * b3v.x + a2 * b2v.x + a3 * b1v.x;
            o.y = Av.y + Lv.y + a1 * b3v.y + a2 * b2v.y + a3 * b1v.y;
            o.z = Av.z + Lv.z + a1 * b3v.z + a2 * b2v.z + a3 * b1v.z;
            o.w = Av.w + Lv.w + a1 * b3v.w + a2 * b2v.w + a3 * b1v.w;
            r4v[m4] = o;
        }
    }
    __syncthreads();

    float s1r[8];
    #pragma unroll
    for (int i = 0; i < 8; i++) s1r[i] = s[i];
    float4 s1v = *(const float4*)&s[(4 * tid) & 7];
    float4 s2v = *(const float4*)&s[O2 + ((4 * tid) & 63)];
    float4 s3v = *(const float4*)&s[O3 + 4 * (tid & 127)];
    float s2f = s[O2 + (tid & 63)], s1f = s[tid & 7];
    float s3a = s[O3 + tid], s3b = s[O3 + tid + 256];

    #pragma unroll
    for (int m4 = 0; m4 < 4; m4++) {
        float a1 = s1r[(tid >> 7) + 2 * m4];
        float a2 = s[O2 + (tid >> 4) + 16 * m4];
        float a3 = s[O3 + (tid >> 1) + 128 * m4];
        r4v[m4].x -= 0.5f * (a1 * s3v.x + a2 * s2v.x + a3 * s1v.x);
        r4v[m4].y -= 0.5f * (a1 * s3v.y + a2 * s2v.y + a3 * s1v.y);
        r4v[m4].z -= 0.5f * (a1 * s3v.z + a2 * s2v.z + a3 * s1v.z);
        r4v[m4].w -= 0.5f * (a1 * s3v.w + a2 * s2v.w + a3 * s1v.w);
    }
    {
        float pa = s1r[tid >> 6] * s2f + s[O2 + (tid >> 3)] * s1f;
        float pb = s1r[(tid >> 6) + 4] * s2f + s[O2 + (tid >> 3) + 32] * s1f;
        P2_3[tid] = pa; P2_3[tid + 256] = pb;
    }
    if (tid < 64) P2_2[tid] = s1r[tid >> 3] * s[tid & 7];
    __syncthreads();

    {
        float4 P23v = *(const float4*)&P2_3[4 * (tid & 127)];
        float4 P22v = *(const float4*)&P2_2[(4 * tid) & 63];
        #pragma unroll
        for (int m4 = 0; m4 < 4; m4++) {
            float a1 = s1r[(tid >> 7) + 2 * m4];
            float a2 = s[O2 + (tid >> 4) + 16 * m4];
            r4v[m4].x += (1.0f / 3.0f) * (a1 * P23v.x + a2 * P22v.x);
            r4v[m4].y += (1.0f / 3.0f) * (a1 * P23v.y + a2 * P22v.y);
            r4v[m4].z += (1.0f / 3.0f) * (a1 * P23v.z + a2 * P22v.z);
            r4v[m4].w += (1.0f / 3.0f) * (a1 * P23v.w + a2 * P22v.w);
        }
        float P22a = P2_2[tid & 63];
        P3_3[tid]       = s1r[tid >> 6] * P22a;
        P3_3[tid + 256] = s1r[(tid >> 6) + 4] * P22a;
    }
    __syncthreads();

    float* S = g_bufA + (size_t)task * STRIDE;
    {
        float4 P33v = *(const float4*)&P3_3[4 * (tid & 127)];
        #pragma unroll
        for (int m4 = 0; m4 < 4; m4++) {
            float a1 = s1r[(tid >> 7) + 2 * m4];
            r4v[m4].x -= 0.25f * a1 * P33v.x;
            r4v[m4].y -= 0.25f * a1 * P33v.y;
            r4v[m4].z -= 0.25f * a1 * P33v.z;
            r4v[m4].w -= 0.25f * a1 * P33v.w;
            *(float4*)&S[O4 + 4 * tid + 1024 * m4] = r4v[m4];
        }
        S[O3 + tid]       = s3a - 0.5f * P2_3[tid]       + (1.0f / 3.0f) * P3_3[tid];
        S[O3 + tid + 256] = s3b - 0.5f * P2_3[tid + 256] + (1.0f / 3.0f) * P3_3[tid + 256];
    }
    if (tid < 64) S[O2 + tid] = s[O2 + tid] - 0.5f * P2_2[tid];
    if (tid < 8)  S[tid] = s1r[tid];
}

// ---------------------------------------------------------------------------
// THE single fused kernel. 384 blocks x 256 threads (3/SM), work-stealing.
// ---------------------------------------------------------------------------
__global__ void __launch_bounds__(NT, 3)
k_fused(const float* __restrict__ x,
        const float* __restrict__ W1,
        const float* __restrict__ b1,
        const float* __restrict__ W2,
        const float* __restrict__ b2,
        float* __restrict__ out)
{
    __shared__ __align__(16) float sm[2848];
    __shared__ int s_task;
    int blk = blockIdx.x;
    int tid = threadIdx.x;

    // warm L2 with W1 for phase 4
    {
        size_t nbytes = (size_t)SIZE * HDIM * 4;
        size_t loff = ((size_t)blk * NT + tid) * 128;
        if (loff < nbytes)
            asm volatile("prefetch.global.L2 [%0];" :: "l"((const char*)W1 + loff));
    }

    // ============ Phase 1: 2-step-fused Chen, 512 stolen tasks =============
    {
        const int l = tid & 7, k = (tid >> 3) & 7, j0 = tid >> 6;
        float* d   = sm;          // 256 = [32][8]
        float* cb0 = sm + 256;    // c2 [0,64), c3 [64,576)
        float* cb1 = sm + 840;
        for (;;) {
            __syncthreads();
            if (tid == 0) s_task = (int)atomicAdd(&g_t1[0], 1u);
            __syncthreads();
            int task = s_task;
            if (task >= NTASK1) break;
            int b = task >> 6, seg = task & 63;

            {   // increments (one per thread: 32 steps x 8 ch = 256)
                int s = tid >> 3, ch = tid & 7;
                int t = seg * SEGST + s;
                float v;
                if (ch < CIN) {
                    float cur  = __ldg(&x[(b * TT + t) * CIN + ch]);
                    float prev = (t > 0) ? __ldg(&x[(b * TT + t - 1) * CIN + ch]) : 0.0f;
                    v = cur - prev;
                } else {
                    v = (t > 0) ? (1.0f / 2047.0f) : 0.0f;
                }
                d[tid] = v;
            }
            __syncthreads();

            float r4[16], c1r[8];
            // ---- iter 0: carry := F(d0, d1) ----
            {
                float al = d[l], bl = d[8 + l], ak = d[k], bk = d[8 + k];
                float bkbl = bk * bl;
                float w1 = ak * ((1.0f / 6.0f) * al + 0.5f * bl) + 0.5f * bkbl;
                float w2 = (1.0f / 6.0f) * bkbl;
                float aje = d[j0], bje = d[8 + j0], ajo = d[j0 + 4], bjo = d[8 + j0 + 4];
                float F3_e = aje * w1 + bje * w2;
                float F3_o = ajo * w1 + bjo * w2;
                float u4 = ak * ((1.0f / 24.0f) * al + (1.0f / 6.0f) * bl) + 0.25f * bkbl;
                float v4 = (1.0f / 6.0f) * bkbl;
                float ge = aje * u4 + bje * v4, he = (1.0f / 24.0f) * bje * bkbl;
                float go = ajo * u4 + bjo * v4, ho = (1.0f / 24.0f) * bjo * bkbl;
                #pragma unroll
                for (int m = 0; m < 16; m++)
                    r4[m] = d[m >> 1] * ((m & 1) ? go : ge)
                          + d[8 + (m >> 1)] * ((m & 1) ? ho : he);
                #pragma unroll
                for (int i = 0; i < 8; i++) c1r[i] = d[i] + d[8 + i];
                cb0[64 + tid] = F3_e;
                cb0[64 + tid + 256] = F3_o;
                if (tid < 64) {
                    int xx = tid >> 3, yy = tid & 7;
                    cb0[tid] = 0.5f * d[xx] * d[yy] + d[xx] * d[8 + yy]
                             + 0.5f * d[8 + xx] * d[8 + yy];
                }
                __syncthreads();
            }
            // ---- iters 1..15 ----
            for (int it = 1; it < 16; it++) {
                float* cc = (it & 1) ? cb0 : cb1;
                float* cn = (it & 1) ? cb1 : cb0;
                const float* da = d + 16 * it;
                const float* db = da + 8;
                float al = da[l], bl = db[l], ak = da[k], bk = db[k];
                float el = al + bl;
                float bkbl = bk * bl;
                float F2_kl = 0.5f * ak * al + ak * bl + 0.5f * bkbl;
                float w1 = ak * ((1.0f / 6.0f) * al + 0.5f * bl) + 0.5f * bkbl;
                float w2 = (1.0f / 6.0f) * bkbl;
                float aje = da[j0], bje = db[j0], ajo = da[j0 + 4], bjo = db[j0 + 4];
                float F3_e = aje * w1 + bje * w2;
                float F3_o = ajo * w1 + bjo * w2;
                float u4 = ak * ((1.0f / 24.0f) * al + (1.0f / 6.0f) * bl) + 0.25f * bkbl;
                float v4 = (1.0f / 6.0f) * bkbl;
                float ge = aje * u4 + bje * v4, he = (1.0f / 24.0f) * bje * bkbl;
                float go = ajo * u4 + bjo * v4, ho = (1.0f / 24.0f) * bjo * bkbl;
                #pragma unroll
                for (int m = 0; m < 16; m++) {
                    float c3v = cc[64 + (tid >> 3) + 32 * m];
                    float c2v = cc[(tid >> 6) + 4 * m];
                    float F3j = (m & 1) ? F3_o : F3_e;
                    float F4m = da[m >> 1] * ((m & 1) ? go : ge)
                              + db[m >> 1] * ((m & 1) ? ho : he);
                    r4[m] += F4m + c1r[m >> 1] * F3j + c2v * F2_kl + c3v * el;
                }
                float t3a = cc[64 + tid] + F3_e + cc[tid >> 3] * el + c1r[j0] * F2_kl;
                float t3b = cc[64 + tid + 256] + F3_o + cc[(tid >> 3) + 32] * el
                          + c1r[j0 + 4] * F2_kl;
                float t2v = 0.0f;
                if (tid < 64) {
                    int xx = tid >> 3, yy = tid & 7;
                    t2v = cc[tid] + 0.5f * da[xx] * da[yy] + da[xx] * db[yy]
                        + 0.5f * db[xx] * db[yy] + c1r[xx] * (da[yy] + db[yy]);
                }
                #pragma unroll
                for (int i = 0; i < 8; i++) c1r[i] += da[i] + db[i];
                cn[64 + tid] = t3a;
                cn[64 + tid + 256] = t3b;
                if (tid < 64) cn[tid] = t2v;
                __syncthreads();
                if ((it & 7) == 7) {   // chunk snapshot
                    float* o = g_bufB + (size_t)(b * NCH + seg * SEGC + (it >> 3)) * STRIDE;
                    o[O3 + tid] = t3a;
                    o[O3 + tid + 256] = t3b;
                    if (tid < 64) o[O2 + tid] = t2v;
                    if (tid < 8)  o[tid] = c1r[tid];
                    #pragma unroll
                    for (int m = 0; m < 16; m++) o[O4 + tid + 256 * m] = r4[m];
                }
            }
        }
    }
    gsync(1);

    // ============ Phase 2: Sklansky over 64 segment totals ==================
    // 6 rounds; 256 merges per round, done by blocks 0..255 (rest idle).
    for (int r = 0; r < 6; r++) {
        if (blk < 256) {
            int b = blk >> 5, g = blk & 31;
            int span = 1 << r;
            int base = (g >> r) << (r + 1);
            int e_src = base + span - 1;
            int e_dst = base + span + (g & (span - 1));
            bool bnew = (g & (span - 1)) == 0;
            const float* A = (r == 0)
                ? g_bufB + (size_t)(b * NCH + e_src * SEGC + SEGC - 1) * STRIDE
                : g_T + (size_t)(b * NSEG2 + e_src) * STRIDE;
            const float* Bp = bnew
                ? g_bufB + (size_t)(b * NCH + e_dst * SEGC + SEGC - 1) * STRIDE
                : g_T + (size_t)(b * NSEG2 + e_dst) * STRIDE;
            float* Od = g_T + (size_t)(b * NSEG2 + e_dst) * STRIDE;
            __syncthreads();
            ta_merge(A, Bp, Od, sm, tid);
        }
        gsync(2 + r);
    }

    // ============ Phase 3: apply + log, 1024 stolen tasks ===================
    for (;;) {
        __syncthreads();
        if (tid == 0) s_task = (int)atomicAdd(&g_t3[0], 1u);
        __syncthreads();
        int task = s_task;
        if (task >= NTASK3) break;
        apply_one(task, sm, tid);
    }
    gsync(8);

    // ============ Phase 4: pool + GEMV partials, 256 stolen tasks ===========
    for (;;) {
        __syncthreads();
        if (tid == 0) s_task = (int)atomicAdd(&g_t4[0], 1u);
        __syncthreads();
        int task = s_task;
        if (task >= NTASK4) break;
        int b = task >> 5, sl = task & 31;
        int i0 = sl * SLW;
        int len = SIZE - i0; if (len > SLW) len = SLW;
        float* pv = sm;
        if (tid < len) {
            const float* p = g_bufA + (size_t)b * NCH * STRIDE + i0 + tid;
            float acc = 0.0f;
            #pragma unroll 8
            for (int n = 0; n < NCH; n++) acc += __ldcg(p + (size_t)n * STRIDE);
            pv[tid] = acc * (1.0f / NCH);
        }
        __syncthreads();
        float acc = 0.0f;
        for (int ii = 0; ii < len; ii++)
            acc = fmaf(pv[ii], __ldg(&W1[(size_t)(i0 + ii) * HDIM + tid]), acc);
        g_hp[(sl * BB + b) * HDIM + tid] = acc;
    }
    gsync(9);

    // ============ Final: MLP head (block 0) =================================
    if (blk == 0) {
        float* red = sm;
        __syncthreads();
        for (int bb = 0; bb < BB; bb++) {
            float h = 0.0f;
            #pragma unroll
            for (int sl2 = 0; sl2 < NSL; sl2++)
                h += __ldcg(&g_hp[(sl2 * BB + bb) * HDIM + tid]);
            float v = fmaxf(h + b1[tid], 0.0f) * W2[tid];
            red[tid] = v; __syncthreads();
            for (int s2 = 128; s2 > 0; s2 >>= 1) {
                if (tid < s2) red[tid] += red[tid + s2];
                __syncthreads();
            }
            if (tid == 0) out[bb] = red[0] + b2[0];
            __syncthreads();
        }
        if (tid == 0) { g_bar[0] = 0u; g_t1[0] = 0u; g_t3[0] = 0u; g_t4[0] = 0u; }
    }
}

// ---------------------------------------------------------------------------
extern "C" void kernel_launch(void* const* d_in, const int* in_sizes, int n_in,
                              void* d_out, int out_size)
{
    const float* x  = (const float*)d_in[0];
    const float* W1 = (const float*)d_in[1];
    const float* b1 = (const float*)d_in[2];
    const float* W2 = (const float*)d_in[3];
    const float* b2 = (const float*)d_in[4];
    float* out = (float*)d_out;

    (void)in_sizes; (void)n_in; (void)out_size;

    k_fused<<<NBLK, NT>>>(x, W1, b1, W2, b2, out);
}

// round 14
// speedup vs baseline: 1.3454x; 1.0307x over previous
#include <cuda_runtime.h>

// Problem constants
#define BB    8
#define TT    2048
#define CIN   7
#define CC    8
#define NCH   128      // chunks per batch
#define SEGC  2        // chunks per segment
#define SEGST 32       // time steps per segment
#define NSEG2 64       // segments per batch
#define NBLK  384      // persistent blocks
#define NT    256      // threads per block
#define SIZE  4680
#define STRIDE 4736
#define O2    8
#define O3    72
#define O4    584
#define HDIM  256
#define NSL   32       // gemv slices
#define SLW   147

// Task list: [0,512) chen | [512,2048) merges (round-major) | [2048,3072) apply
//            | [3072,3328) gemv
#define T_MERGE0 512
#define T_APPLY0 2048
#define T_GEMV0  3072
#define NTOT     3328

// Scratch (device globals -- no runtime allocation)
__device__ __align__(16) float g_bufB[(size_t)BB * NCH * STRIDE];   // chunk prefixes
__device__ __align__(16) float g_bufA[(size_t)BB * NCH * STRIDE];   // logs
__device__ __align__(16) float g_S[(size_t)BB * NSEG2 * 6 * STRIDE]; // versioned merge slots
__device__ __align__(16) float g_hp[NSL * BB * HDIM];
// Sync state (zero-init; reset at end of launch). Stride-8 padding.
__device__ __align__(128) unsigned int g_task[32];
__device__ __align__(128) unsigned int g_totF[BB * NSEG2 * 8];   // segment rows ready
__device__ __align__(128) unsigned int g_updC[BB * NSEG2 * 8];   // merge version counters
__device__ __align__(128) unsigned int g_appC[BB * 32];          // applies done per batch
__device__ __align__(128) unsigned int g_done[32];               // gemv tasks done
__device__ __align__(128) unsigned int g_exit[32];               // blocks exited loop

__device__ __forceinline__ void waitGE(volatile unsigned int* p, unsigned int v)
{
    while (*p < v) { }
}

// slot (b, e, v) for v >= 1; v == 0 lives in g_bufB (segment total row)
__device__ __forceinline__ const float* rowptr(int b, int e, int v)
{
    if (v == 0) return g_bufB + (size_t)(b * NCH + e * SEGC + 1) * STRIDE;
    return g_S + (size_t)(((b << 6) | e) * 6 + (v - 1)) * STRIDE;
}
__device__ __forceinline__ float* slotptr(int b, int e, int v)
{
    return g_S + (size_t)(((b << 6) | e) * 6 + (v - 1)) * STRIDE;
}

// ---------------------------------------------------------------------------
// Group merge Od = A (x) B. 256 threads. smem: al, bl (584 each).
// ---------------------------------------------------------------------------
__device__ void ta_merge(const float* __restrict__ A, const float* __restrict__ Bp,
                         float* __restrict__ Od, float* sm, int tid)
{
    float* al = sm;
    float* bl = sm + 584;
    for (int t = tid; t < O4; t += NT) { al[t] = __ldcg(A + t); bl[t] = __ldcg(Bp + t); }
    __syncthreads();

    for (int t = tid; t < O4; t += NT) {
        float r;
        if (t >= O3) {
            int q = t - O3;
            r = al[t] + bl[t] + al[q >> 6] * bl[O2 + (q & 63)]
              + al[O2 + (q >> 3)] * bl[q & 7];
        } else if (t >= O2) {
            int u = t - O2;
            r = al[t] + bl[t] + al[u >> 3] * bl[u & 7];
        } else {
            r = al[t] + bl[t];
        }
        Od[t] = r;
    }
    float a1r[8];
    #pragma unroll
    for (int i = 0; i < 8; i++) a1r[i] = al[i];
    float4 b1v = *(const float4*)&bl[(4 * tid) & 7];
    float4 b2v = *(const float4*)&bl[O2 + ((4 * tid) & 63)];
    float4 b3v = *(const float4*)&bl[O3 + 4 * (tid & 127)];
    #pragma unroll
    for (int m4 = 0; m4 < 4; m4++) {
        int p = 4 * tid + 1024 * m4;
        float a1 = a1r[(tid >> 7) + 2 * m4];
        float a2 = al[O2 + (tid >> 4) + 16 * m4];
        float a3 = al[O3 + (tid >> 1) + 128 * m4];
        float4 Av = __ldcg((const float4*)(A + O4 + p));
        float4 Bv = __ldcg((const float4*)(Bp + O4 + p));
        float4 o;
        o.x = Av.x + Bv.x + a1 * b3v.x + a2 * b2v.x + a3 * b1v.x;
        o.y = Av.y + Bv.y + a1 * b3v.y + a2 * b2v.y + a3 * b1v.y;
        o.z = Av.z + Bv.z + a1 * b3v.z + a2 * b2v.z + a3 * b1v.z;
        o.w = Av.w + Bv.w + a1 * b3v.w + a2 * b2v.w + a3 * b1v.w;
        *(float4*)(Od + O4 + p) = o;
    }
}

// ---------------------------------------------------------------------------
// apply+log for chunk (b, n); A = offset row (final prefix) or null for seg 0.
// ---------------------------------------------------------------------------
__device__ void apply_one(int b, int n, const float* __restrict__ A,
                          float* sm, int tid)
{
    float* s    = sm;
    float* al   = sm + 584;
    float* blw  = sm + 1168;
    float* P2_2 = sm + 1752;
    float* P2_3 = sm + 1824;
    float* P3_3 = sm + 2336;

    const float* L = g_bufB + (size_t)(b * NCH + n) * STRIDE;
    float4 r4v[4];

    if (A == 0) {
        for (int t = tid; t < O4; t += NT) s[t] = __ldcg(L + t);
        #pragma unroll
        for (int m4 = 0; m4 < 4; m4++)
            r4v[m4] = __ldcg((const float4*)(L + O4 + 4 * tid + 1024 * m4));
    } else {
        for (int t = tid; t < O4; t += NT) { al[t] = __ldcg(A + t); blw[t] = __ldcg(L + t); }
        __syncthreads();
        for (int t = tid; t < O4; t += NT) {
            float r;
            if (t >= O3) {
                int q = t - O3;
                r = al[t] + blw[t]
                  + al[q >> 6]        * blw[O2 + (q & 63)]
                  + al[O2 + (q >> 3)] * blw[q & 7];
            } else if (t >= O2) {
                int u = t - O2;
                r = al[t] + blw[t] + al[u >> 3] * blw[u & 7];
            } else {
                r = al[t] + blw[t];
            }
            s[t] = r;
        }
        float a1r[8];
        #pragma unroll
        for (int i = 0; i < 8; i++) a1r[i] = al[i];
        float4 b1v = *(const float4*)&blw[(4 * tid) & 7];
        float4 b2v = *(const float4*)&blw[O2 + ((4 * tid) & 63)];
        float4 b3v = *(const float4*)&blw[O3 + 4 * (tid & 127)];
        #pragma unroll
        for (int m4 = 0; m4 < 4; m4++) {
            int p = 4 * tid + 1024 * m4;
            float a1 = a1r[(tid >> 7) + 2 * m4];
            float a2 = al[O2 + (tid >> 4) + 16 * m4];
            float a3 = al[O3 + (tid >> 1) + 128 * m4];
            float4 Av = __ldcg((const float4*)(A + O4 + p));
            float4 Lv = __ldcg((const float4*)(L + O4 + p));
            float4 o;
            o.x = Av.x + Lv.x + a1 * b3v.x + a2 * b2v.x + a3 * b1v.x;
            o.y = Av.y + Lv.y + a1 * b3v.y + a2 * b2v.y + a3 * b1v.y;
            o.z = Av.z + Lv.z + a1 * b3v.z + a2 * b2v.z + a3 * b1v.z;
            o.w = Av.w + Lv.w + a1 * b3v.w + a2 * b2v.w + a3 * b1v.w;
            r4v[m4] = o;
        }
    }
    __syncthreads();

    float s1r[8];
    #pragma unroll
    for (int i = 0; i < 8; i++) s1r[i] = s[i];
    float4 s1v = *(const float4*)&s[(4 * tid) & 7];
    float4 s2v = *(const float4*)&s[O2 + ((4 * tid) & 63)];
    float4 s3v = *(const float4*)&s[O3 + 4 * (tid & 127)];
    float s2f = s[O2 + (tid & 63)], s1f = s[tid & 7];
    float s3a = s[O3 + tid], s3b = s[O3 + tid + 256];

    #pragma unroll
    for (int m4 = 0; m4 < 4; m4++) {
        float a1 = s1r[(tid >> 7) + 2 * m4];
        float a2 = s[O2 + (tid >> 4) + 16 * m4];
        float a3 = s[O3 + (tid >> 1) + 128 * m4];
        r4v[m4].x -= 0.5f * (a1 * s3v.x + a2 * s2v.x + a3 * s1v.x);
        r4v[m4].y -= 0.5f * (a1 * s3v.y + a2 * s2v.y + a3 * s1v.y);
        r4v[m4].z -= 0.5f * (a1 * s3v.z + a2 * s2v.z + a3 * s1v.z);
        r4v[m4].w -= 0.5f * (a1 * s3v.w + a2 * s2v.w + a3 * s1v.w);
    }
    {
        float pa = s1r[tid >> 6] * s2f + s[O2 + (tid >> 3)] * s1f;
        float pb = s1r[(tid >> 6) + 4] * s2f + s[O2 + (tid >> 3) + 32] * s1f;
        P2_3[tid] = pa; P2_3[tid + 256] = pb;
    }
    if (tid < 64) P2_2[tid] = s1r[tid >> 3] * s[tid & 7];
    __syncthreads();

    {
        float4 P23v = *(const float4*)&P2_3[4 * (tid & 127)];
        float4 P22v = *(const float4*)&P2_2[(4 * tid) & 63];
        #pragma unroll
        for (int m4 = 0; m4 < 4; m4++) {
            float a1 = s1r[(tid >> 7) + 2 * m4];
            float a2 = s[O2 + (tid >> 4) + 16 * m4];
            r4v[m4].x += (1.0f / 3.0f) * (a1 * P23v.x + a2 * P22v.x);
            r4v[m4].y += (1.0f / 3.0f) * (a1 * P23v.y + a2 * P22v.y);
            r4v[m4].z += (1.0f / 3.0f) * (a1 * P23v.z + a2 * P22v.z);
            r4v[m4].w += (1.0f / 3.0f) * (a1 * P23v.w + a2 * P22v.w);
        }
        float P22a = P2_2[tid & 63];
        P3_3[tid]       = s1r[tid >> 6] * P22a;
        P3_3[tid + 256] = s1r[(tid >> 6) + 4] * P22a;
    }
    __syncthreads();

    float* S = g_bufA + (size_t)(b * NCH + n) * STRIDE;
    {
        float4 P33v = *(const float4*)&P3_3[4 * (tid & 127)];
        #pragma unroll
        for (int m4 = 0; m4 < 4; m4++) {
            float a1 = s1r[(tid >> 7) + 2 * m4];
            r4v[m4].x -= 0.25f * a1 * P33v.x;
            r4v[m4].y -= 0.25f * a1 * P33v.y;
            r4v[m4].z -= 0.25f * a1 * P33v.z;
            r4v[m4].w -= 0.25f * a1 * P33v.w;
            *(float4*)&S[O4 + 4 * tid + 1024 * m4] = r4v[m4];
        }
        S[O3 + tid]       = s3a - 0.5f * P2_3[tid]       + (1.0f / 3.0f) * P3_3[tid];
        S[O3 + tid + 256] = s3b - 0.5f * P2_3[tid + 256] + (1.0f / 3.0f) * P3_3[tid + 256];
    }
    if (tid < 64) S[O2 + tid] = s[O2 + tid] - 0.5f * P2_2[tid];
    if (tid < 8)  S[tid] = s1r[tid];
}

// ---------------------------------------------------------------------------
// THE single fused dataflow kernel. 384 blocks x 256 threads, 3/SM.
// ---------------------------------------------------------------------------
__global__ void __launch_bounds__(NT, 3)
k_fused(const float* __restrict__ x,
        const float* __restrict__ W1,
        const float* __restrict__ b1,
        const float* __restrict__ W2,
        const float* __restrict__ b2,
        float* __restrict__ out)
{
    __shared__ __align__(16) float sm[2848];
    __shared__ int s_task;
    int blk = blockIdx.x;
    int tid = threadIdx.x;

    // warm L2 with W1
    {
        size_t nbytes = (size_t)SIZE * HDIM * 4;
        size_t loff = ((size_t)blk * NT + tid) * 128;
        if (loff < nbytes)
            asm volatile("prefetch.global.L2 [%0];" :: "l"((const char*)W1 + loff));
    }

    const int l = tid & 7, k = (tid >> 3) & 7, j0 = tid >> 6;

    for (;;) {
        __syncthreads();
        if (tid == 0) s_task = (int)atomicAdd(&g_task[0], 1u);
        __syncthreads();
        int t = s_task;
        if (t >= NTOT) break;

        if (t < T_MERGE0) {
            // ================= Chen task: segment (b, seg) ===================
            int b = t >> 6, seg = t & 63;
            float* d   = sm;
            float* cb0 = sm + 256;
            float* cb1 = sm + 840;
            {
                int s = tid >> 3, ch = tid & 7;
                int tt = seg * SEGST + s;
                float v;
                if (ch < CIN) {
                    float cur  = __ldg(&x[(b * TT + tt) * CIN + ch]);
                    float prev = (tt > 0) ? __ldg(&x[(b * TT + tt - 1) * CIN + ch]) : 0.0f;
                    v = cur - prev;
                } else {
                    v = (tt > 0) ? (1.0f / 2047.0f) : 0.0f;
                }
                d[tid] = v;
            }
            __syncthreads();

            float r4[16], c1r[8];
            {
                float al = d[l], bl = d[8 + l], ak = d[k], bk = d[8 + k];
                float bkbl = bk * bl;
                float w1 = ak * ((1.0f / 6.0f) * al + 0.5f * bl) + 0.5f * bkbl;
                float w2 = (1.0f / 6.0f) * bkbl;
                float aje = d[j0], bje = d[8 + j0], ajo = d[j0 + 4], bjo = d[8 + j0 + 4];
                float F3_e = aje * w1 + bje * w2;
                float F3_o = ajo * w1 + bjo * w2;
                float u4 = ak * ((1.0f / 24.0f) * al + (1.0f / 6.0f) * bl) + 0.25f * bkbl;
                float v4 = (1.0f / 6.0f) * bkbl;
                float ge = aje * u4 + bje * v4, he = (1.0f / 24.0f) * bje * bkbl;
                float go = ajo * u4 + bjo * v4, ho = (1.0f / 24.0f) * bjo * bkbl;
                #pragma unroll
                for (int m = 0; m < 16; m++)
                    r4[m] = d[m >> 1] * ((m & 1) ? go : ge)
                          + d[8 + (m >> 1)] * ((m & 1) ? ho : he);
                #pragma unroll
                for (int i = 0; i < 8; i++) c1r[i] = d[i] + d[8 + i];
                cb0[64 + tid] = F3_e;
                cb0[64 + tid + 256] = F3_o;
                if (tid < 64) {
                    int xx = tid >> 3, yy = tid & 7;
                    cb0[tid] = 0.5f * d[xx] * d[yy] + d[xx] * d[8 + yy]
                             + 0.5f * d[8 + xx] * d[8 + yy];
                }
                __syncthreads();
            }
            for (int it = 1; it < 16; it++) {
                float* cc = (it & 1) ? cb0 : cb1;
                float* cn = (it & 1) ? cb1 : cb0;
                const float* da = d + 16 * it;
                const float* db = da + 8;
                float al = da[l], bl = db[l], ak = da[k], bk = db[k];
                float el = al + bl;
                float bkbl = bk * bl;
                float F2_kl = 0.5f * ak * al + ak * bl + 0.5f * bkbl;
                float w1 = ak * ((1.0f / 6.0f) * al + 0.5f * bl) + 0.5f * bkbl;
                float w2 = (1.0f / 6.0f) * bkbl;
                float aje = da[j0], bje = db[j0], ajo = da[j0 + 4], bjo = db[j0 + 4];
                float F3_e = aje * w1 + bje * w2;
                float F3_o = ajo * w1 + bjo * w2;
                float u4 = ak * ((1.0f / 24.0f) * al + (1.0f / 6.0f) * bl) + 0.25f * bkbl;
                float v4 = (1.0f / 6.0f) * bkbl;
                float ge = aje * u4 + bje * v4, he = (1.0f / 24.0f) * bje * bkbl;
                float go = ajo * u4 + bjo * v4, ho = (1.0f / 24.0f) * bjo * bkbl;
                #pragma unroll
                for (int m = 0; m < 16; m++) {
                    float c3v = cc[64 + (tid >> 3) + 32 * m];
                    float c2v = cc[(tid >> 6) + 4 * m];
                    float F3j = (m & 1) ? F3_o : F3_e;
                    float F4m = da[m >> 1] * ((m & 1) ? go : ge)
                              + db[m >> 1] * ((m & 1) ? ho : he);
                    r4[m] += F4m + c1r[m >> 1] * F3j + c2v * F2_kl + c3v * el;
                }
                float t3a = cc[64 + tid] + F3_e + cc[tid >> 3] * el + c1r[j0] * F2_kl;
                float t3b = cc[64 + tid + 256] + F3_o + cc[(tid >> 3) + 32] * el
                          + c1r[j0 + 4] * F2_kl;
                float t2v = 0.0f;
                if (tid < 64) {
                    int xx = tid >> 3, yy = tid & 7;
                    t2v = cc[tid] + 0.5f * da[xx] * da[yy] + da[xx] * db[yy]
                        + 0.5f * db[xx] * db[yy] + c1r[xx] * (da[yy] + db[yy]);
                }
                #pragma unroll
                for (int i = 0; i < 8; i++) c1r[i] += da[i] + db[i];
                cn[64 + tid] = t3a;
                cn[64 + tid + 256] = t3b;
                if (tid < 64) cn[tid] = t2v;
                __syncthreads();
                if ((it & 7) == 7) {
                    float* o = g_bufB + (size_t)(b * NCH + seg * SEGC + (it >> 3)) * STRIDE;
                    o[O3 + tid] = t3a;
                    o[O3 + tid + 256] = t3b;
                    if (tid < 64) o[O2 + tid] = t2v;
                    if (tid < 8)  o[tid] = c1r[tid];
                    #pragma unroll
                    for (int m = 0; m < 16; m++) o[O4 + tid + 256 * m] = r4[m];
                }
            }
            __syncthreads();
            if (tid == 0) {
                __threadfence();
                atomicExch(&g_totF[((b << 6) | seg) * 8], 1u);
            }
        } else if (t < T_APPLY0) {
            // ================= Merge task (round-major Sklansky) =============
            int idx = t - T_MERGE0;
            int r = idx >> 8, j = idx & 255;
            int b = j >> 5, g = j & 31;
            int span = 1 << r;
            int base = (g >> r) << (r + 1);
            int src = base + span - 1;
            int dst = base + span + (g & (span - 1));
            if (dst != 63) {           // dst==63 consumed by nobody: skip
                int vprev = __popc(dst & (span - 1));
                if (tid == 0) {
                    if (r == 0) waitGE(&g_totF[((b << 6) | src) * 8], 1u);
                    else        waitGE(&g_updC[((b << 6) | src) * 8], (unsigned)r);
                    if (vprev == 0) waitGE(&g_totF[((b << 6) | dst) * 8], 1u);
                    else            waitGE(&g_updC[((b << 6) | dst) * 8], (unsigned)vprev);
                    __threadfence();
                }
                __syncthreads();
                const float* A  = rowptr(b, src, r);
                const float* Bp = rowptr(b, dst, vprev);
                float* Od = slotptr(b, dst, vprev + 1);
                ta_merge(A, Bp, Od, sm, tid);
                __syncthreads();
                if (tid == 0) {
                    __threadfence();
                    atomicMax(&g_updC[((b << 6) | dst) * 8], (unsigned)(vprev + 1));
                }
            }
        } else if (t < T_GEMV0) {
            // ================= Apply task (b, n) =============================
            int idx = t - T_APPLY0;
            int b = idx >> 7, n = idx & 127;
            int seg = n >> 1;
            if (tid == 0) {
                waitGE(&g_totF[((b << 6) | seg) * 8], 1u);   // local rows ready
                if (seg >= 1) {
                    int e = seg - 1, vf = __popc(e);
                    if (vf == 0) waitGE(&g_totF[(b << 6) * 8], 1u);
                    else         waitGE(&g_updC[((b << 6) | e) * 8], (unsigned)vf);
                }
                __threadfence();
            }
            __syncthreads();
            const float* A = 0;
            if (seg >= 1) A = rowptr(b, seg - 1, __popc(seg - 1));
            apply_one(b, n, A, sm, tid);
            __syncthreads();
            if (tid == 0) {
                __threadfence();
                atomicAdd(&g_appC[b * 32], 1u);
            }
        } else {
            // ================= Pool + GEMV task (b, sl) ======================
            int idx = t - T_GEMV0;
            int b = idx >> 5, sl = idx & 31;
            if (tid == 0) { waitGE(&g_appC[b * 32], NCH); __threadfence(); }
            __syncthreads();
            int i0 = sl * SLW;
            int len = SIZE - i0; if (len > SLW) len = SLW;
            float* pv = sm;
            if (tid < len) {
                const float* p = g_bufA + (size_t)b * NCH * STRIDE + i0 + tid;
                float acc = 0.0f;
                #pragma unroll 8
                for (int n = 0; n < NCH; n++) acc += __ldcg(p + (size_t)n * STRIDE);
                pv[tid] = acc * (1.0f / NCH);
            }
            __syncthreads();
            float acc = 0.0f;
            for (int ii = 0; ii < len; ii++)
                acc = fmaf(pv[ii], __ldg(&W1[(size_t)(i0 + ii) * HDIM + tid]), acc);
            g_hp[(sl * BB + b) * HDIM + tid] = acc;
            __syncthreads();
            if (tid == 0) { __threadfence(); atomicAdd(&g_done[0], 1u); }
        }
    }

    // exit ack
    if (tid == 0) atomicAdd(&g_exit[0], 1u);

    // ============ Final: MLP head + state reset (block 0) ===================
    if (blk == 0) {
        if (tid == 0) { waitGE(&g_done[0], BB * NSL); __threadfence(); }
        __syncthreads();
        float* red = sm;
        for (int bb = 0; bb < BB; bb++) {
            float h = 0.0f;
            #pragma unroll
            for (int sl2 = 0; sl2 < NSL; sl2++)
                h += __ldcg(&g_hp[(sl2 * BB + bb) * HDIM + tid]);
            float v = fmaxf(h + b1[tid], 0.0f) * W2[tid];
            red[tid] = v; __syncthreads();
            for (int s2 = 128; s2 > 0; s2 >>= 1) {
                if (tid < s2) red[tid] += red[tid + s2];
                __syncthreads();
            }
            if (tid == 0) out[bb] = red[0] + b2[0];
            __syncthreads();
        }
        // reset (safe: all blocks have acked past all flag reads)
        if (tid == 0) waitGE(&g_exit[0], NBLK);
        __syncthreads();
        for (int i = tid; i < BB * NSEG2; i += NT) {
            g_totF[i * 8] = 0u;
            g_updC[i * 8] = 0u;
        }
        if (tid < BB) g_appC[tid * 32] = 0u;
        if (tid == 0) { g_done[0] = 0u; g_task[0] = 0u; g_exit[0] = 0u; }
    }
}

// ---------------------------------------------------------------------------
extern "C" void kernel_launch(void* const* d_in, const int* in_sizes, int n_in,
                              void* d_out, int out_size)
{
    const float* x  = (const float*)d_in[0];
    const float* W1 = (const float*)d_in[1];
    const float* b1 = (const float*)d_in[2];
    const float* W2 = (const float*)d_in[3];
    const float* b2 = (const float*)d_in[4];
    float* out = (float*)d_out;

    (void)in_sizes; (void)n_in; (void)out_size;

    k_fused<<<NBLK, NT>>>(x, W1, b1, W2, b2, out);
}

// round 15
// speedup vs baseline: 1.4218x; 1.0568x over previous
#include <cuda_runtime.h>

// Problem constants
#define BB    8
#define TT    2048
#define CIN   7
#define CC    8
#define NCH   128      // chunks per batch
#define SEGC  2        // chunks per segment
#define SEGST 32       // time steps per segment
#define NSEG2 64       // segments per batch
#define NBLK  384      // persistent blocks
#define NT    256      // threads per block
#define SIZE  4680
#define STRIDE 4736
#define O2    8
#define O3    72
#define O4    584
#define HDIM  256
#define NSL   32       // gemv slices
#define SLW   147

#define NTASK1 (BB * NSEG2)    // 512 chen tasks
#define NTASK3 (BB * NCH)      // 1024 apply tasks
#define NTASK4 (BB * NSL)      // 256 pool/gemv tasks

// Scratch (device globals -- no runtime allocation)
__device__ __align__(16) float g_bufB[(size_t)BB * NCH * STRIDE];   // local prefixes
__device__ __align__(16) float g_bufA[(size_t)BB * NCH * STRIDE];   // logs
__device__ __align__(16) float g_T[(size_t)BB * NSEG2 * STRIDE];    // scanned totals P[e]
__device__ __align__(16) float g_hp[NSL * BB * HDIM];
// Sync state: each counter on its OWN 128B line.
__device__ __align__(128) unsigned int g_bar[32];
__device__ __align__(128) unsigned int g_t1[32];
__device__ __align__(128) unsigned int g_t3[32];
__device__ __align__(128) unsigned int g_t4[32];

// ---------------------------------------------------------------------------
// Device-wide barrier. Co-residency: __launch_bounds__(256,3) -> 444 >= 384.
// ---------------------------------------------------------------------------
__device__ __forceinline__ void gsync(unsigned int idx)
{
    __syncthreads();
    if (threadIdx.x == 0) {
        __threadfence();
        atomicAdd(&g_bar[0], 1u);
        unsigned int target = idx * NBLK;
        volatile unsigned int* p = &g_bar[0];
        while (*p < target) { }
        __threadfence();
    }
    __syncthreads();
}

// ---------------------------------------------------------------------------
// Group merge Od = A (x) B. 256 threads. smem: al, bl (584 each).
// ---------------------------------------------------------------------------
__device__ void ta_merge(const float* __restrict__ A, const float* __restrict__ Bp,
                         float* __restrict__ Od, float* sm, int tid)
{
    float* al = sm;
    float* bl = sm + 584;
    for (int t = tid; t < O4; t += NT) { al[t] = __ldcg(A + t); bl[t] = __ldcg(Bp + t); }
    __syncthreads();

    for (int t = tid; t < O4; t += NT) {
        float r;
        if (t >= O3) {
            int q = t - O3;
            r = al[t] + bl[t] + al[q >> 6] * bl[O2 + (q & 63)]
              + al[O2 + (q >> 3)] * bl[q & 7];
        } else if (t >= O2) {
            int u = t - O2;
            r = al[t] + bl[t] + al[u >> 3] * bl[u & 7];
        } else {
            r = al[t] + bl[t];
        }
        Od[t] = r;
    }
    float a1r[8];
    #pragma unroll
    for (int i = 0; i < 8; i++) a1r[i] = al[i];
    float4 b1v = *(const float4*)&bl[(4 * tid) & 7];
    float4 b2v = *(const float4*)&bl[O2 + ((4 * tid) & 63)];
    float4 b3v = *(const float4*)&bl[O3 + 4 * (tid & 127)];
    #pragma unroll
    for (int m4 = 0; m4 < 4; m4++) {
        int p = 4 * tid + 1024 * m4;
        float a1 = a1r[(tid >> 7) + 2 * m4];
        float a2 = al[O2 + (tid >> 4) + 16 * m4];
        float a3 = al[O3 + (tid >> 1) + 128 * m4];
        float4 Av = __ldcg((const float4*)(A + O4 + p));
        float4 Bv = __ldcg((const float4*)(Bp + O4 + p));
        float4 o;
        o.x = Av.x + Bv.x + a1 * b3v.x + a2 * b2v.x + a3 * b1v.x;
        o.y = Av.y + Bv.y + a1 * b3v.y + a2 * b2v.y + a3 * b1v.y;
        o.z = Av.z + Bv.z + a1 * b3v.z + a2 * b2v.z + a3 * b1v.z;
        o.w = Av.w + Bv.w + a1 * b3v.w + a2 * b2v.w + a3 * b1v.w;
        *(float4*)(Od + O4 + p) = o;
    }
}

// ---------------------------------------------------------------------------
// apply+log: group element = A (x) L (or just L if A == 0); log -> S.
// ---------------------------------------------------------------------------
__device__ void apply_one(const float* __restrict__ L, const float* __restrict__ A,
                          float* __restrict__ S, float* sm, int tid)
{
    float* s    = sm;
    float* al   = sm + 584;
    float* blw  = sm + 1168;
    float* P2_2 = sm + 1752;
    float* P2_3 = sm + 1824;
    float* P3_3 = sm + 2336;

    float4 r4v[4];

    if (A == 0) {
        for (int t = tid; t < O4; t += NT) s[t] = __ldcg(L + t);
        #pragma unroll
        for (int m4 = 0; m4 < 4; m4++)
            r4v[m4] = __ldcg((const float4*)(L + O4 + 4 * tid + 1024 * m4));
    } else {
        for (int t = tid; t < O4; t += NT) { al[t] = __ldcg(A + t); blw[t] = __ldcg(L + t); }
        __syncthreads();
        for (int t = tid; t < O4; t += NT) {
            float r;
            if (t >= O3) {
                int q = t - O3;
                r = al[t] + blw[t]
                  + al[q >> 6]        * blw[O2 + (q & 63)]
                  + al[O2 + (q >> 3)] * blw[q & 7];
            } else if (t >= O2) {
                int u = t - O2;
                r = al[t] + blw[t] + al[u >> 3] * blw[u & 7];
            } else {
                r = al[t] + blw[t];
            }
            s[t] = r;
        }
        float a1r[8];
        #pragma unroll
        for (int i = 0; i < 8; i++) a1r[i] = al[i];
        float4 b1v = *(const float4*)&blw[(4 * tid) & 7];
        float4 b2v = *(const float4*)&blw[O2 + ((4 * tid) & 63)];
        float4 b3v = *(const float4*)&blw[O3 + 4 * (tid & 127)];
        #pragma unroll
        for (int m4 = 0; m4 < 4; m4++) {
            int p = 4 * tid + 1024 * m4;
            float a1 = a1r[(tid >> 7) + 2 * m4];
            float a2 = al[O2 + (tid >> 4) + 16 * m4];
            float a3 = al[O3 + (tid >> 1) + 128 * m4];
            float4 Av = __ldcg((const float4*)(A + O4 + p));
            float4 Lv = __ldcg((const float4*)(L + O4 + p));
            float4 o;
            o.x = Av.x + Lv.x + a1 * b3v.x + a2 * b2v.x + a3 * b1v.x;
            o.y = Av.y + Lv.y + a1 * b3v.y + a2 * b2v.y + a3 * b1v.y;
            o.z = Av.z + Lv.z + a1 * b3v.z + a2 * b2v.z + a3 * b1v.z;
            o.w = Av.w + Lv.w + a1 * b3v.w + a2 * b2v.w + a3 * b1v.w;
            r4v[m4] = o;
        }
    }
    __syncthreads();

    float s1r[8];
    #pragma unroll
    for (int i = 0; i < 8; i++) s1r[i] = s[i];
    float4 s1v = *(const float4*)&s[(4 * tid) & 7];
    float4 s2v = *(const float4*)&s[O2 + ((4 * tid) & 63)];
    float4 s3v = *(const float4*)&s[O3 + 4 * (tid & 127)];
    float s2f = s[O2 + (tid & 63)], s1f = s[tid & 7];
    float s3a = s[O3 + tid], s3b = s[O3 + tid + 256];

    #pragma unroll
    for (int m4 = 0; m4 < 4; m4++) {
        float a1 = s1r[(tid >> 7) + 2 * m4];
        float a2 = s[O2 + (tid >> 4) + 16 * m4];
        float a3 = s[O3 + (tid >> 1) + 128 * m4];
        r4v[m4].x -= 0.5f * (a1 * s3v.x + a2 * s2v.x + a3 * s1v.x);
        r4v[m4].y -= 0.5f * (a1 * s3v.y + a2 * s2v.y + a3 * s1v.y);
        r4v[m4].z -= 0.5f * (a1 * s3v.z + a2 * s2v.z + a3 * s1v.z);
        r4v[m4].w -= 0.5f * (a1 * s3v.w + a2 * s2v.w + a3 * s1v.w);
    }
    {
        float pa = s1r[tid >> 6] * s2f + s[O2 + (tid >> 3)] * s1f;
        float pb = s1r[(tid >> 6) + 4] * s2f + s[O2 + (tid >> 3) + 32] * s1f;
        P2_3[tid] = pa; P2_3[tid + 256] = pb;
    }
    if (tid < 64) P2_2[tid] = s1r[tid >> 3] * s[tid & 7];
    __syncthreads();

    {
        float4 P23v = *(const float4*)&P2_3[4 * (tid & 127)];
        float4 P22v = *(const float4*)&P2_2[(4 * tid) & 63];
        #pragma unroll
        for (int m4 = 0; m4 < 4; m4++) {
            float a1 = s1r[(tid >> 7) + 2 * m4];
            float a2 = s[O2 + (tid >> 4) + 16 * m4];
            r4v[m4].x += (1.0f / 3.0f) * (a1 * P23v.x + a2 * P22v.x);
            r4v[m4].y += (1.0f / 3.0f) * (a1 * P23v.y + a2 * P22v.y);
            r4v[m4].z += (1.0f / 3.0f) * (a1 * P23v.z + a2 * P22v.z);
            r4v[m4].w += (1.0f / 3.0f) * (a1 * P23v.w + a2 * P22v.w);
        }
        float P22a = P2_2[tid & 63];
        P3_3[tid]       = s1r[tid >> 6] * P22a;
        P3_3[tid + 256] = s1r[(tid >> 6) + 4] * P22a;
    }
    __syncthreads();

    {
        float4 P33v = *(const float4*)&P3_3[4 * (tid & 127)];
        #pragma unroll
        for (int m4 = 0; m4 < 4; m4++) {
            float a1 = s1r[(tid >> 7) + 2 * m4];
            r4v[m4].x -= 0.25f * a1 * P33v.x;
            r4v[m4].y -= 0.25f * a1 * P33v.y;
            r4v[m4].z -= 0.25f * a1 * P33v.z;
            r4v[m4].w -= 0.25f * a1 * P33v.w;
            *(float4*)&S[O4 + 4 * tid + 1024 * m4] = r4v[m4];
        }
        S[O3 + tid]       = s3a - 0.5f * P2_3[tid]       + (1.0f / 3.0f) * P3_3[tid];
        S[O3 + tid + 256] = s3b - 0.5f * P2_3[tid + 256] + (1.0f / 3.0f) * P3_3[tid + 256];
    }
    if (tid < 64) S[O2 + tid] = s[O2 + tid] - 0.5f * P2_2[tid];
    if (tid < 8)  S[tid] = s1r[tid];
}

// ---------------------------------------------------------------------------
// THE single fused kernel. 384 blocks x 256 threads (3/SM), work-stealing.
// ---------------------------------------------------------------------------
__global__ void __launch_bounds__(NT, 3)
k_fused(const float* __restrict__ x,
        const float* __restrict__ W1,
        const float* __restrict__ b1,
        const float* __restrict__ W2,
        const float* __restrict__ b2,
        float* __restrict__ out)
{
    __shared__ __align__(16) float sm[2848];
    __shared__ int s_task;
    int blk = blockIdx.x;
    int tid = threadIdx.x;

    // warm L2 with W1 for phase 4
    {
        size_t nbytes = (size_t)SIZE * HDIM * 4;
        size_t loff = ((size_t)blk * NT + tid) * 128;
        if (loff < nbytes)
            asm volatile("prefetch.global.L2 [%0];" :: "l"((const char*)W1 + loff));
    }

    // ============ Phase 1: 2-step-fused Chen, 512 stolen tasks =============
    {
        const int l = tid & 7, k = (tid >> 3) & 7, j0 = tid >> 6;
        float* d   = sm;          // 256 = [32][8]
        float* cb0 = sm + 256;    // c2 [0,64), c3 [64,576)
        float* cb1 = sm + 840;
        for (;;) {
            __syncthreads();
            if (tid == 0) s_task = (int)atomicAdd(&g_t1[0], 1u);
            __syncthreads();
            int task = s_task;
            if (task >= NTASK1) break;
            int b = task >> 6, seg = task & 63;

            {   // increments (one per thread: 32 steps x 8 ch = 256)
                int s = tid >> 3, ch = tid & 7;
                int t = seg * SEGST + s;
                float v;
                if (ch < CIN) {
                    float cur  = __ldg(&x[(b * TT + t) * CIN + ch]);
                    float prev = (t > 0) ? __ldg(&x[(b * TT + t - 1) * CIN + ch]) : 0.0f;
                    v = cur - prev;
                } else {
                    v = (t > 0) ? (1.0f / 2047.0f) : 0.0f;
                }
                d[tid] = v;
            }
            __syncthreads();

            float r4[16], c1r[8];
            // ---- iter 0: carry := F(d0, d1) ----
            {
                float al = d[l], bl = d[8 + l], ak = d[k], bk = d[8 + k];
                float bkbl = bk * bl;
                float w1 = ak * ((1.0f / 6.0f) * al + 0.5f * bl) + 0.5f * bkbl;
                float w2 = (1.0f / 6.0f) * bkbl;
                float aje = d[j0], bje = d[8 + j0], ajo = d[j0 + 4], bjo = d[8 + j0 + 4];
                float F3_e = aje * w1 + bje * w2;
                float F3_o = ajo * w1 + bjo * w2;
                float u4 = ak * ((1.0f / 24.0f) * al + (1.0f / 6.0f) * bl) + 0.25f * bkbl;
                float v4 = (1.0f / 6.0f) * bkbl;
                float ge = aje * u4 + bje * v4, he = (1.0f / 24.0f) * bje * bkbl;
                float go = ajo * u4 + bjo * v4, ho = (1.0f / 24.0f) * bjo * bkbl;
                #pragma unroll
                for (int m = 0; m < 16; m++)
                    r4[m] = d[m >> 1] * ((m & 1) ? go : ge)
                          + d[8 + (m >> 1)] * ((m & 1) ? ho : he);
                #pragma unroll
                for (int i = 0; i < 8; i++) c1r[i] = d[i] + d[8 + i];
                cb0[64 + tid] = F3_e;
                cb0[64 + tid + 256] = F3_o;
                if (tid < 64) {
                    int xx = tid >> 3, yy = tid & 7;
                    cb0[tid] = 0.5f * d[xx] * d[yy] + d[xx] * d[8 + yy]
                             + 0.5f * d[8 + xx] * d[8 + yy];
                }
                __syncthreads();
            }
            // ---- iters 1..15 ----
            for (int it = 1; it < 16; it++) {
                float* cc = (it & 1) ? cb0 : cb1;
                float* cn = (it & 1) ? cb1 : cb0;
                const float* da = d + 16 * it;
                const float* db = da + 8;
                float al = da[l], bl = db[l], ak = da[k], bk = db[k];
                float el = al + bl;
                float bkbl = bk * bl;
                float F2_kl = 0.5f * ak * al + ak * bl + 0.5f * bkbl;
                float w1 = ak * ((1.0f / 6.0f) * al + 0.5f * bl) + 0.5f * bkbl;
                float w2 = (1.0f / 6.0f) * bkbl;
                float aje = da[j0], bje = db[j0], ajo = da[j0 + 4], bjo = db[j0 + 4];
                float F3_e = aje * w1 + bje * w2;
                float F3_o = ajo * w1 + bjo * w2;
                float u4 = ak * ((1.0f / 24.0f) * al + (1.0f / 6.0f) * bl) + 0.25f * bkbl;
                float v4 = (1.0f / 6.0f) * bkbl;
                float ge = aje * u4 + bje * v4, he = (1.0f / 24.0f) * bje * bkbl;
                float go = ajo * u4 + bjo * v4, ho = (1.0f / 24.0f) * bjo * bkbl;
                #pragma unroll
                for (int m = 0; m < 16; m++) {
                    float c3v = cc[64 + (tid >> 3) + 32 * m];
                    float c2v = cc[(tid >> 6) + 4 * m];
                    float F3j = (m & 1) ? F3_o : F3_e;
                    float F4m = da[m >> 1] * ((m & 1) ? go : ge)
                              + db[m >> 1] * ((m & 1) ? ho : he);
                    r4[m] += F4m + c1r[m >> 1] * F3j + c2v * F2_kl + c3v * el;
                }
                float t3a = cc[64 + tid] + F3_e + cc[tid >> 3] * el + c1r[j0] * F2_kl;
                float t3b = cc[64 + tid + 256] + F3_o + cc[(tid >> 3) + 32] * el
                          + c1r[j0 + 4] * F2_kl;
                float t2v = 0.0f;
                if (tid < 64) {
                    int xx = tid >> 3, yy = tid & 7;
                    t2v = cc[tid] + 0.5f * da[xx] * da[yy] + da[xx] * db[yy]
                        + 0.5f * db[xx] * db[yy] + c1r[xx] * (da[yy] + db[yy]);
                }
                #pragma unroll
                for (int i = 0; i < 8; i++) c1r[i] += da[i] + db[i];
                cn[64 + tid] = t3a;
                cn[64 + tid + 256] = t3b;
                if (tid < 64) cn[tid] = t2v;
                __syncthreads();
                if ((it & 7) == 7) {   // chunk snapshot
                    float* o = g_bufB + (size_t)(b * NCH + seg * SEGC + (it >> 3)) * STRIDE;
                    o[O3 + tid] = t3a;
                    o[O3 + tid + 256] = t3b;
                    if (tid < 64) o[O2 + tid] = t2v;
                    if (tid < 8)  o[tid] = c1r[tid];
                    #pragma unroll
                    for (int m = 0; m < 16; m++) o[O4 + tid + 256 * m] = r4[m];
                }
            }
        }
    }
    gsync(1);

    // ============ Phase 2: Sklansky over 64 segment totals ==================
    // 6 rounds; 256 merges per round, done by blocks 0..255 (rest idle).
    for (int r = 0; r < 6; r++) {
        if (blk < 256) {
            int b = blk >> 5, g = blk & 31;
            int span = 1 << r;
            int base = (g >> r) << (r + 1);
            int e_src = base + span - 1;
            int e_dst = base + span + (g & (span - 1));
            bool bnew = (g & (span - 1)) == 0;
            const float* A = (r == 0)
                ? g_bufB + (size_t)(b * NCH + e_src * SEGC + SEGC - 1) * STRIDE
                : g_T + (size_t)(b * NSEG2 + e_src) * STRIDE;
            const float* Bp = bnew
                ? g_bufB + (size_t)(b * NCH + e_dst * SEGC + SEGC - 1) * STRIDE
                : g_T + (size_t)(b * NSEG2 + e_dst) * STRIDE;
            float* Od = g_T + (size_t)(b * NSEG2 + e_dst) * STRIDE;
            __syncthreads();
            ta_merge(A, Bp, Od, sm, tid);
        }
        gsync(2 + r);
    }

    // ============ Phase 3: apply + log, 1024 stolen tasks ===================
    // Odd chunk 2s+1: prefix == P[s] (already computed) -> log-only.
    // Even chunk 2s : prefix == P[s-1] (x) local(2s)   -> merge + log.
    for (;;) {
        __syncthreads();
        if (tid == 0) s_task = (int)atomicAdd(&g_t3[0], 1u);
        __syncthreads();
        int task = s_task;
        if (task >= NTASK3) break;
        int b = task >> 7, n = task & 127;
        int seg = n >> 1;
        const float* L;
        const float* A;
        if (n & 1) {
            // log-only: group element is P[seg]
            L = (seg == 0)
                ? g_bufB + (size_t)(b * NCH + 1) * STRIDE
                : g_T + (size_t)(b * NSEG2 + seg) * STRIDE;
            A = 0;
        } else {
            L = g_bufB + (size_t)(b * NCH + n) * STRIDE;
            A = (seg == 0) ? 0
              : (seg == 1) ? g_bufB + (size_t)(b * NCH + 1) * STRIDE
                           : g_T + (size_t)(b * NSEG2 + seg - 1) * STRIDE;
        }
        float* S = g_bufA + (size_t)(b * NCH + n) * STRIDE;
        apply_one(L, A, S, sm, tid);
    }
    gsync(8);

    // ============ Phase 4: pool + GEMV partials, 256 stolen tasks ===========
    for (;;) {
        __syncthreads();
        if (tid == 0) s_task = (int)atomicAdd(&g_t4[0], 1u);
        __syncthreads();
        int task = s_task;
        if (task >= NTASK4) break;
        int b = task >> 5, sl = task & 31;
        int i0 = sl * SLW;
        int len = SIZE - i0; if (len > SLW) len = SLW;
        float* pv = sm;
        if (tid < len) {
            const float* p = g_bufA + (size_t)b * NCH * STRIDE + i0 + tid;
            float acc = 0.0f;
            #pragma unroll 8
            for (int n = 0; n < NCH; n++) acc += __ldcg(p + (size_t)n * STRIDE);
            pv[tid] = acc * (1.0f / NCH);
        }
        __syncthreads();
        float acc = 0.0f;
        for (int ii = 0; ii < len; ii++)
            acc = fmaf(pv[ii], __ldg(&W1[(size_t)(i0 + ii) * HDIM + tid]), acc);
        g_hp[(sl * BB + b) * HDIM + tid] = acc;
    }
    gsync(9);

    // ============ Final: MLP head (block 0) =================================
    if (blk == 0) {
        float* red = sm;
        __syncthreads();
        for (int bb = 0; bb < BB; bb++) {
            float h = 0.0f;
            #pragma unroll
            for (int sl2 = 0; sl2 < NSL; sl2++)
                h += __ldcg(&g_hp[(sl2 * BB + bb) * HDIM + tid]);
            float v = fmaxf(h + b1[tid], 0.0f) * W2[tid];
            red[tid] = v; __syncthreads();
            for (int s2 = 128; s2 > 0; s2 >>= 1) {
                if (tid < s2) red[tid] += red[tid + s2];
                __syncthreads();
            }
            if (tid == 0) out[bb] = red[0] + b2[0];
            __syncthreads();
        }
        if (tid == 0) { g_bar[0] = 0u; g_t1[0] = 0u; g_t3[0] = 0u; g_t4[0] = 0u; }
    }
}

// ---------------------------------------------------------------------------
extern "C" void kernel_launch(void* const* d_in, const int* in_sizes, int n_in,
                              void* d_out, int out_size)
{
    const float* x  = (const float*)d_in[0];
    const float* W1 = (const float*)d_in[1];
    const float* b1 = (const float*)d_in[2];
    const float* W2 = (const float*)d_in[3];
    const float* b2 = (const float*)d_in[4];
    float* out = (float*)d_out;

    (void)in_sizes; (void)n_in; (void)out_size;

    k_fused<<<NBLK, NT>>>(x, W1, b1, W2, b2, out);
}